// round 13
// baseline (speedup 1.0000x reference)
#include <cuda_runtime.h>
#include <cuda_bf16.h>
#include <cstdint>

// ---------------------------------------------------------------------------
// Problem constants
// ---------------------------------------------------------------------------
#define D_MODEL   512
#define D_HALF    256
#define D_FF      1024
#define D_FF2     2048
#define N_LAYERS  2
#define N_EXPERTS 8
#define N_TOKENS  2048
#define CAP       2048

// GEMM smem staging
#define AS_STRIDE 36
#define BS_STRIDE 136
#define A_WORDS   (128 * AS_STRIDE)          // 4608
#define B_WORDS   (32 * BS_STRIDE)           // 4352
#define STAGE_WORDS (A_WORDS + B_WORDS)      // 8960
#define NSTAGE    2
#define GEMM_SMEM (STAGE_WORDS * NSTAGE * 4) // 71680 bytes -> 2 CTAs/SM

// ---------------------------------------------------------------------------
// Static scratch (no allocations allowed)
// ---------------------------------------------------------------------------
__device__ float d_Xg [(size_t)N_EXPERTS * CAP * D_MODEL];
__device__ float d_H  [(size_t)N_EXPERTS * CAP * D_FF];
__device__ float d_A2 [(size_t)N_EXPERTS * CAP * D_FF2];
__device__ float d_H2 [(size_t)N_EXPERTS * CAP * D_FF];
__device__ float d_Ob [(size_t)N_EXPERTS * CAP * D_MODEL];
__device__ int   d_counts[N_EXPERTS];
__device__ int   d_tlist[N_EXPERTS * CAP];

// ---------------------------------------------------------------------------
// Helpers
// ---------------------------------------------------------------------------
__device__ __forceinline__ float gelu_f(float v) {
    return 0.5f * v * (1.0f + erff(v * 0.70710678118654752440f));
}

__device__ __forceinline__ uint32_t smem_u32(const void* p) {
    uint32_t a;
    asm("{ .reg .u64 t; cvta.to.shared.u64 t, %1; cvt.u32.u64 %0, t; }" : "=r"(a) : "l"(p));
    return a;
}

__device__ __forceinline__ void cp16(uint32_t dst, const void* src, int szbytes) {
    asm volatile("cp.async.cg.shared.global [%0], [%1], 16, %2;"
                 :: "r"(dst), "l"(src), "r"(szbytes));
}
__device__ __forceinline__ void cp16f(uint32_t dst, const void* src) {
    asm volatile("cp.async.cg.shared.global [%0], [%1], 16;"
                 :: "r"(dst), "l"(src));
}
__device__ __forceinline__ void cp_commit() {
    asm volatile("cp.async.commit_group;" ::: "memory");
}
template<int N>
__device__ __forceinline__ void cp_wait() {
    asm volatile("cp.async.wait_group %0;" :: "n"(N) : "memory");
}

// m16n8k8 tf32 mma: D += A(16x8 row) * B(8x8 col)
__device__ __forceinline__ void mma_tf32_16n8k8(float* c, const uint32_t* a,
                                                const uint32_t* b) {
    asm volatile(
        "mma.sync.aligned.m16n8k8.row.col.f32.tf32.tf32.f32 "
        "{%0,%1,%2,%3}, {%4,%5,%6,%7}, {%8,%9}, {%0,%1,%2,%3};"
        : "+f"(c[0]), "+f"(c[1]), "+f"(c[2]), "+f"(c[3])
        : "r"(a[0]), "r"(a[1]), "r"(a[2]), "r"(a[3]), "r"(b[0]), "r"(b[1]));
}

__device__ __forceinline__ float reduce256(float v, float* red) {
    int t = threadIdx.x;
    red[t] = v;
    __syncthreads();
    #pragma unroll
    for (int s = 128; s > 0; s >>= 1) {
        if (t < s) red[t] += red[t + s];
        __syncthreads();
    }
    float r = red[0];
    __syncthreads();
    return r;
}

__device__ __forceinline__ void tf_round(uint32_t& a, uint32_t& b, int r) {
    a += b;
    b = (b << r) | (b >> (32 - r));
    b ^= a;
}

__device__ __forceinline__ uint2 threefry2x32(uint32_t k0, uint32_t k1,
                                              uint32_t x0, uint32_t x1) {
    uint32_t ks0 = k0, ks1 = k1, ks2 = k0 ^ k1 ^ 0x1BD11BDAu;
    x0 += ks0; x1 += ks1;
    tf_round(x0, x1, 13); tf_round(x0, x1, 15); tf_round(x0, x1, 26); tf_round(x0, x1, 6);
    x0 += ks1; x1 += ks2 + 1u;
    tf_round(x0, x1, 17); tf_round(x0, x1, 29); tf_round(x0, x1, 16); tf_round(x0, x1, 24);
    x0 += ks2; x1 += ks0 + 2u;
    tf_round(x0, x1, 13); tf_round(x0, x1, 15); tf_round(x0, x1, 26); tf_round(x0, x1, 6);
    x0 += ks0; x1 += ks1 + 3u;
    tf_round(x0, x1, 17); tf_round(x0, x1, 29); tf_round(x0, x1, 16); tf_round(x0, x1, 24);
    x0 += ks1; x1 += ks2 + 4u;
    tf_round(x0, x1, 13); tf_round(x0, x1, 15); tf_round(x0, x1, 26); tf_round(x0, x1, 6);
    x0 += ks2; x1 += ks0 + 5u;
    return make_uint2(x0, x1);
}

// ---------------------------------------------------------------------------
// Kernel: zero routing counters
// ---------------------------------------------------------------------------
__global__ void zero_counts_kernel() {
    if (threadIdx.x < N_EXPERTS) d_counts[threadIdx.x] = 0;
}

// ---------------------------------------------------------------------------
// Kernel: policy head + Gumbel top-2 routing.  One block per token.
// ---------------------------------------------------------------------------
__global__ __launch_bounds__(256)
void routing_kernel(const float* __restrict__ x,
                    const float* __restrict__ pw1, const float* __restrict__ pb1,
                    const float* __restrict__ pg1, const float* __restrict__ pbb1,
                    const float* __restrict__ pw2, const float* __restrict__ pb2) {
    __shared__ float xs[D_MODEL];
    __shared__ float red[256];
    __shared__ float gbuf[D_HALF];
    __shared__ float scores[N_EXPERTS];

    int token = blockIdx.x;
    int t = threadIdx.x;

    for (int i = t; i < D_MODEL; i += 256) xs[i] = x[(size_t)token * D_MODEL + i];
    __syncthreads();

    float acc = pb1[t];
    #pragma unroll 4
    for (int k = 0; k < D_MODEL; k++)
        acc = fmaf(xs[k], pw1[k * D_HALF + t], acc);

    float mean = reduce256(acc, red) * (1.0f / D_HALF);
    float d = acc - mean;
    float var = reduce256(d * d, red) * (1.0f / D_HALF);
    float hn = d * rsqrtf(var + 1e-5f) * pg1[t] + pbb1[t];
    gbuf[t] = gelu_f(hn);
    __syncthreads();

    if (t < N_EXPERTS) {
        float lg = pb2[t];
        #pragma unroll 4
        for (int j = 0; j < D_HALF; j++)
            lg = fmaf(gbuf[j], pw2[j * N_EXPERTS + t], lg);

        // partitionable threefry: counter (0, i), bits = out0 ^ out1
        uint32_t idx = (uint32_t)(token * N_EXPERTS + t);
        uint2 r = threefry2x32(0u, 42u, 0u, idx);
        uint32_t bits = r.x ^ r.y;
        float u = __uint_as_float((bits >> 9) | 0x3f800000u) - 1.0f;
        float gn = -logf(-logf(u + 1e-10f) + 1e-10f);
        scores[t] = lg + gn;
    }
    __syncthreads();

    if (t == 0) {
        int e1 = 0; float v1 = scores[0];
        #pragma unroll
        for (int e = 1; e < N_EXPERTS; e++)
            if (scores[e] > v1) { v1 = scores[e]; e1 = e; }
        int e2 = -1; float v2 = -1e30f;
        #pragma unroll
        for (int e = 0; e < N_EXPERTS; e++) {
            if (e == e1) continue;
            if (scores[e] > v2) { v2 = scores[e]; e2 = e; }
        }
        int p = atomicAdd(&d_counts[e1], 1);
        d_tlist[e1 * CAP + p] = token;
        p = atomicAdd(&d_counts[e2], 1);
        d_tlist[e2 * CAP + p] = token;
    }
}

// ---------------------------------------------------------------------------
// Kernel: gather selected token rows
// ---------------------------------------------------------------------------
__global__ void gather_kernel(const float* __restrict__ x) {
    int m = blockIdx.x, e = blockIdx.y;
    if (m >= d_counts[e]) return;
    int token = d_tlist[e * CAP + m];
    const float4* src = (const float4*)(x + (size_t)token * D_MODEL);
    float4* dst = (float4*)(d_Xg + ((size_t)e * CAP + m) * D_MODEL);
    dst[threadIdx.x] = src[threadIdx.x];
}

// ---------------------------------------------------------------------------
// tf32 tensor-core GEMM, cp.async 2-stage ping-pong, 128 threads (4 warps),
// warp tile 64x64 (2x2 warp grid) to halve smem fragment re-reads:
//   C[e] = act(A[e] @ B[e] + bias[e]),  A: [M_e,K] rm,  B: [K,N] rm.
// Tile 128x128x32; per warp: 4(mt) x 8(nt) m16n8k8 = 32 MMA/kstep.
// grid (N/128, CAP/128, N_EXPERTS), 128 threads, dyn smem = GEMM_SMEM.
// ---------------------------------------------------------------------------
template<int ACT>
__global__ __launch_bounds__(128, 2)
void gemm_mma(const float* __restrict__ Aall, long strideA,
              const float* __restrict__ Ball, long strideB,
              const float* __restrict__ biasAll, long strideBias,
              float* __restrict__ Call, long strideC,
              int N, int K) {
    extern __shared__ uint32_t sm[];

    int e = blockIdx.z;
    int M = d_counts[e];
    int m0 = blockIdx.y * 128;
    if (m0 >= M) return;
    int n0 = blockIdx.x * 128;

    const float* A    = Aall   + (long)e * strideA;
    const float* B    = Ball   + (long)e * strideB;
    const float* bias = biasAll + (long)e * strideBias;
    float* C          = Call   + (long)e * strideC;

    int tid  = threadIdx.x;
    int wid  = tid >> 5;
    int lane = tid & 31;
    int wm = wid >> 1;            // 0..1  (m)
    int wn = wid & 1;             // 0..1  (n)
    int gid = lane >> 2;          // 0..7
    int tig = lane & 3;           // 0..3

    float acc[4][8][4];
    #pragma unroll
    for (int i = 0; i < 4; i++)
        #pragma unroll
        for (int j = 0; j < 8; j++)
            #pragma unroll
            for (int c = 0; c < 4; c++) acc[i][j][c] = 0.0f;

    const int NC = K >> 5;

    auto load_tile = [&](int chunk) {
        uint32_t* As = sm + (chunk & 1) * STAGE_WORDS;
        uint32_t* Bs = As + A_WORDS;
        int k0 = chunk << 5;
        #pragma unroll
        for (int i = 0; i < 8; i++) {
            int idx = i * 128 + tid;
            int r = idx >> 3, c4 = (idx & 7) << 2;
            int rr = m0 + r;
            int sz = (rr < M) ? 16 : 0;
            int rc = (rr < M) ? rr : 0;
            cp16(smem_u32(&As[r * AS_STRIDE + c4]),
                 &A[(long)rc * K + k0 + c4], sz);
        }
        #pragma unroll
        for (int i = 0; i < 8; i++) {
            int idx = i * 128 + tid;
            int r = idx >> 5, c4 = (idx & 31) << 2;
            cp16f(smem_u32(&Bs[r * BS_STRIDE + c4]),
                  &B[(long)(k0 + r) * N + n0 + c4]);
        }
        cp_commit();
    };

    load_tile(0);

    for (int chunk = 0; chunk < NC; chunk++) {
        if (chunk + 1 < NC) { load_tile(chunk + 1); cp_wait<1>(); }
        else                { cp_wait<0>(); }
        __syncthreads();

        const uint32_t* As = sm + (chunk & 1) * STAGE_WORDS;
        const uint32_t* Bs = As + A_WORDS;

        #pragma unroll
        for (int ks = 0; ks < 4; ks++) {
            int kk = ks * 8;
            uint32_t a[4][4];
            #pragma unroll
            for (int mt = 0; mt < 4; mt++) {
                int row = wm * 64 + mt * 16 + gid;
                const uint32_t* ap = &As[row * AS_STRIDE + kk + tig];
                a[mt][0] = ap[0];
                a[mt][1] = ap[8 * AS_STRIDE];
                a[mt][2] = ap[4];
                a[mt][3] = ap[8 * AS_STRIDE + 4];
            }
            uint32_t b[8][2];
            #pragma unroll
            for (int nt = 0; nt < 8; nt++) {
                int col = wn * 64 + nt * 8 + gid;
                b[nt][0] = Bs[(kk + tig) * BS_STRIDE + col];
                b[nt][1] = Bs[(kk + tig + 4) * BS_STRIDE + col];
            }
            #pragma unroll
            for (int mt = 0; mt < 4; mt++)
                #pragma unroll
                for (int nt = 0; nt < 8; nt++)
                    mma_tf32_16n8k8(acc[mt][nt], a[mt], b[nt]);
        }
        __syncthreads();
    }

    // epilogue: bias + act, float2 stores
    #pragma unroll
    for (int mt = 0; mt < 4; mt++) {
        #pragma unroll
        for (int nt = 0; nt < 8; nt++) {
            int col = n0 + wn * 64 + nt * 8 + 2 * tig;
            float b0 = bias[col], b1 = bias[col + 1];
            int r0 = m0 + wm * 64 + mt * 16 + gid;
            int r1 = r0 + 8;
            if (r0 < M) {
                float v0 = acc[mt][nt][0] + b0;
                float v1 = acc[mt][nt][1] + b1;
                if (ACT == 1) { v0 = gelu_f(v0); v1 = gelu_f(v1); }
                *(float2*)&C[(long)r0 * N + col] = make_float2(v0, v1);
            }
            if (r1 < M) {
                float v0 = acc[mt][nt][2] + b0;
                float v1 = acc[mt][nt][3] + b1;
                if (ACT == 1) { v0 = gelu_f(v0); v1 = gelu_f(v1); }
                *(float2*)&C[(long)r1 * N + col] = make_float2(v0, v1);
            }
        }
    }
}

// ---------------------------------------------------------------------------
// Kernel: per-row LN of h2, sigmoid gate from h, residual update.
// ---------------------------------------------------------------------------
__global__ __launch_bounds__(256)
void lngate_kernel(const float* __restrict__ ng, const float* __restrict__ nb,
                   const float* __restrict__ gwv) {
    __shared__ float red[256];
    int m = blockIdx.x, e = blockIdx.y;
    if (m >= d_counts[e]) return;
    int t = threadIdx.x;

    float* h = d_H + ((size_t)e * CAP + m) * D_FF;
    const float* h2 = d_H2 + ((size_t)e * CAP + m) * D_FF;
    const float* ng_e = ng + (size_t)e * (N_LAYERS * D_FF);
    const float* nb_e = nb + (size_t)e * (N_LAYERS * D_FF);
    const float* gw_e = gwv + (size_t)e * (N_LAYERS * D_FF);

    float hv[4], h2v[4];
    float s = 0.f, sq = 0.f, dot = 0.f;
    #pragma unroll
    for (int c = 0; c < 4; c++) {
        int i = t + c * 256;
        hv[c] = h[i];
        h2v[c] = h2[i];
        s += h2v[c];
        dot = fmaf(hv[c], gw_e[i], dot);
    }
    float mean = reduce256(s, red) * (1.0f / D_FF);
    #pragma unroll
    for (int c = 0; c < 4; c++) { float d = h2v[c] - mean; sq += d * d; }
    float var = reduce256(sq, red) * (1.0f / D_FF);
    float dtot = reduce256(dot, red);
    float gate = 1.0f / (1.0f + expf(-dtot));
    float rstd = rsqrtf(var + 1e-5f);

    #pragma unroll
    for (int c = 0; c < 4; c++) {
        int i = t + c * 256;
        float hn = (h2v[c] - mean) * rstd * ng_e[i] + nb_e[i];
        h[i] = hv[c] + gate * hn;
    }
}

// ---------------------------------------------------------------------------
// Kernel: final residual LN + scatter-add into output.
// ---------------------------------------------------------------------------
__global__ __launch_bounds__(256)
void final_kernel(const float* __restrict__ x,
                  const float* __restrict__ fng, const float* __restrict__ fnb,
                  float* __restrict__ out) {
    __shared__ float red[256];
    int m = blockIdx.x, e = blockIdx.y;
    if (m >= d_counts[e]) return;
    int t = threadIdx.x;
    int token = d_tlist[e * CAP + m];

    const float* orow = d_Ob + ((size_t)e * CAP + m) * D_MODEL;
    const float* xrow = x + (size_t)token * D_MODEL;
    const float* g = fng + (size_t)e * D_MODEL;
    const float* b = fnb + (size_t)e * D_MODEL;

    float v[2];
    float s = 0.f, sq = 0.f;
    #pragma unroll
    for (int c = 0; c < 2; c++) {
        int i = t + c * 256;
        v[c] = xrow[i] + orow[i];
        s += v[c];
    }
    float mean = reduce256(s, red) * (1.0f / D_MODEL);
    #pragma unroll
    for (int c = 0; c < 2; c++) { float d = v[c] - mean; sq += d * d; }
    float var = reduce256(sq, red) * (1.0f / D_MODEL);
    float rstd = rsqrtf(var + 1e-5f);

    #pragma unroll
    for (int c = 0; c < 2; c++) {
        int i = t + c * 256;
        float y = (v[c] - mean) * rstd * g[i] + b[i];
        atomicAdd(&out[(size_t)token * D_MODEL + i], y);
    }
}

// ---------------------------------------------------------------------------
// Launch
// ---------------------------------------------------------------------------
extern "C" void kernel_launch(void* const* d_in, const int* in_sizes, int n_in,
                              void* d_out, int out_size) {
    const float* x    = (const float*)d_in[0];
    const float* pw1  = (const float*)d_in[1];
    const float* pb1  = (const float*)d_in[2];
    const float* pg1  = (const float*)d_in[3];
    const float* pbb1 = (const float*)d_in[4];
    const float* pw2  = (const float*)d_in[5];
    const float* pb2  = (const float*)d_in[6];
    const float* Win  = (const float*)d_in[7];
    const float* b_in = (const float*)d_in[8];
    const float* W1   = (const float*)d_in[9];
    const float* b1   = (const float*)d_in[10];
    const float* W2   = (const float*)d_in[11];
    const float* b2   = (const float*)d_in[12];
    const float* ng   = (const float*)d_in[13];
    const float* nb   = (const float*)d_in[14];
    const float* gw   = (const float*)d_in[15];
    const float* Wout = (const float*)d_in[16];
    const float* bout = (const float*)d_in[17];
    const float* fng  = (const float*)d_in[18];
    const float* fnb  = (const float*)d_in[19];
    float* out = (float*)d_out;

    float *Xg, *H, *A2, *H2, *Ob;
    cudaGetSymbolAddress((void**)&Xg, d_Xg);
    cudaGetSymbolAddress((void**)&H,  d_H);
    cudaGetSymbolAddress((void**)&A2, d_A2);
    cudaGetSymbolAddress((void**)&H2, d_H2);
    cudaGetSymbolAddress((void**)&Ob, d_Ob);

    cudaFuncSetAttribute(gemm_mma<0>, cudaFuncAttributeMaxDynamicSharedMemorySize, GEMM_SMEM);
    cudaFuncSetAttribute(gemm_mma<1>, cudaFuncAttributeMaxDynamicSharedMemorySize, GEMM_SMEM);

    cudaMemsetAsync(out, 0, (size_t)out_size * sizeof(float), 0);
    zero_counts_kernel<<<1, 32>>>();
    routing_kernel<<<N_TOKENS, 256>>>(x, pw1, pb1, pg1, pbb1, pw2, pb2);
    gather_kernel<<<dim3(CAP, N_EXPERTS), 128>>>(x);

    // H = Xg @ Win + b_in                  [M,512] x [512,1024]
    gemm_mma<0><<<dim3(D_FF / 128, CAP / 128, N_EXPERTS), 128, GEMM_SMEM>>>(
        Xg, (long)CAP * D_MODEL,
        Win, (long)D_MODEL * D_FF,
        b_in, (long)D_FF,
        H, (long)CAP * D_FF,
        D_FF, D_MODEL);

    for (int l = 0; l < N_LAYERS; l++) {
        // A2 = gelu(H @ W1[l] + b1[l])     [M,1024] x [1024,2048]
        gemm_mma<1><<<dim3(D_FF2 / 128, CAP / 128, N_EXPERTS), 128, GEMM_SMEM>>>(
            H, (long)CAP * D_FF,
            W1 + (long)l * D_FF * D_FF2, (long)N_LAYERS * D_FF * D_FF2,
            b1 + (long)l * D_FF2, (long)N_LAYERS * D_FF2,
            A2, (long)CAP * D_FF2,
            D_FF2, D_FF);
        // H2 = A2 @ W2[l] + b2[l]          [M,2048] x [2048,1024]
        gemm_mma<0><<<dim3(D_FF / 128, CAP / 128, N_EXPERTS), 128, GEMM_SMEM>>>(
            A2, (long)CAP * D_FF2,
            W2 + (long)l * D_FF2 * D_FF, (long)N_LAYERS * D_FF2 * D_FF,
            b2 + (long)l * D_FF, (long)N_LAYERS * D_FF,
            H2, (long)CAP * D_FF,
            D_FF, D_FF2);
        lngate_kernel<<<dim3(CAP, N_EXPERTS), 256>>>(
            ng + (long)l * D_FF, nb + (long)l * D_FF, gw + (long)l * D_FF);
    }

    // Ob = H @ Wout + bout                 [M,1024] x [1024,512]
    gemm_mma<0><<<dim3(D_MODEL / 128, CAP / 128, N_EXPERTS), 128, GEMM_SMEM>>>(
        H, (long)CAP * D_FF,
        Wout, (long)D_FF * D_MODEL,
        bout, (long)D_MODEL,
        Ob, (long)CAP * D_MODEL,
        D_MODEL, D_FF);

    final_kernel<<<dim3(CAP, N_EXPERTS), 256>>>(x, fng, fnb, out);
}

// round 14
// speedup vs baseline: 2.0024x; 2.0024x over previous
#include <cuda_runtime.h>
#include <cuda_fp16.h>
#include <cstdint>

// ---------------------------------------------------------------------------
// Problem constants
// ---------------------------------------------------------------------------
#define D_MODEL   512
#define D_HALF    256
#define D_FF      1024
#define D_FF2     2048
#define N_LAYERS  2
#define N_EXPERTS 8
#define N_TOKENS  2048
#define CAP       2048

// fp16 GEMM smem staging: tile 128x128, BK=64 halves
#define AS_ST     72                          // halves per row (64 + 8 pad)
#define A_HALVES  (128 * AS_ST)               // 9216
#define B_HALVES  (128 * AS_ST)               // 9216  (B stored [n][k])
#define STAGE_H   (A_HALVES + B_HALVES)       // 18432 halves
#define GEMM_SMEM (STAGE_H * 2 * 2)           // 73728 bytes -> 2 CTAs/SM

// ---------------------------------------------------------------------------
// Static scratch (no allocations allowed)
// ---------------------------------------------------------------------------
__device__ __half d_Xg16[(size_t)N_EXPERTS * CAP * D_MODEL];
__device__ float  d_H   [(size_t)N_EXPERTS * CAP * D_FF];
__device__ __half d_H16 [(size_t)N_EXPERTS * CAP * D_FF];
__device__ __half d_A216[(size_t)N_EXPERTS * CAP * D_FF2];
__device__ float  d_H2  [(size_t)N_EXPERTS * CAP * D_FF];
__device__ float  d_Ob  [(size_t)N_EXPERTS * CAP * D_MODEL];
__device__ int    d_counts[N_EXPERTS];
__device__ int    d_tlist[N_EXPERTS * CAP];
// fp16 transposed weights [rows=N][K]
__device__ __half d_WinT [(size_t)N_EXPERTS * D_FF * D_MODEL];
__device__ __half d_W1T  [(size_t)N_EXPERTS * N_LAYERS * D_FF2 * D_FF];
__device__ __half d_W2T  [(size_t)N_EXPERTS * N_LAYERS * D_FF * D_FF2];
__device__ __half d_WoutT[(size_t)N_EXPERTS * D_MODEL * D_FF];

// ---------------------------------------------------------------------------
// Helpers
// ---------------------------------------------------------------------------
__device__ __forceinline__ float gelu_f(float v) {
    return 0.5f * v * (1.0f + erff(v * 0.70710678118654752440f));
}

__device__ __forceinline__ uint32_t smem_u32(const void* p) {
    uint32_t a;
    asm("{ .reg .u64 t; cvta.to.shared.u64 t, %1; cvt.u32.u64 %0, t; }" : "=r"(a) : "l"(p));
    return a;
}

__device__ __forceinline__ void cp16(uint32_t dst, const void* src, int szbytes) {
    asm volatile("cp.async.cg.shared.global [%0], [%1], 16, %2;"
                 :: "r"(dst), "l"(src), "r"(szbytes));
}
__device__ __forceinline__ void cp16f(uint32_t dst, const void* src) {
    asm volatile("cp.async.cg.shared.global [%0], [%1], 16;"
                 :: "r"(dst), "l"(src));
}
__device__ __forceinline__ void cp_commit() {
    asm volatile("cp.async.commit_group;" ::: "memory");
}
template<int N>
__device__ __forceinline__ void cp_wait() {
    asm volatile("cp.async.wait_group %0;" :: "n"(N) : "memory");
}

// m16n8k16 fp16 mma, fp32 accum
__device__ __forceinline__ void mma_f16_16n8k16(float* c, const uint32_t* a,
                                                const uint32_t* b) {
    asm volatile(
        "mma.sync.aligned.m16n8k16.row.col.f32.f16.f16.f32 "
        "{%0,%1,%2,%3}, {%4,%5,%6,%7}, {%8,%9}, {%0,%1,%2,%3};"
        : "+f"(c[0]), "+f"(c[1]), "+f"(c[2]), "+f"(c[3])
        : "r"(a[0]), "r"(a[1]), "r"(a[2]), "r"(a[3]), "r"(b[0]), "r"(b[1]));
}

__device__ __forceinline__ float reduce256(float v, float* red) {
    int t = threadIdx.x;
    red[t] = v;
    __syncthreads();
    #pragma unroll
    for (int s = 128; s > 0; s >>= 1) {
        if (t < s) red[t] += red[t + s];
        __syncthreads();
    }
    float r = red[0];
    __syncthreads();
    return r;
}

__device__ __forceinline__ void tf_round(uint32_t& a, uint32_t& b, int r) {
    a += b;
    b = (b << r) | (b >> (32 - r));
    b ^= a;
}

__device__ __forceinline__ uint2 threefry2x32(uint32_t k0, uint32_t k1,
                                              uint32_t x0, uint32_t x1) {
    uint32_t ks0 = k0, ks1 = k1, ks2 = k0 ^ k1 ^ 0x1BD11BDAu;
    x0 += ks0; x1 += ks1;
    tf_round(x0, x1, 13); tf_round(x0, x1, 15); tf_round(x0, x1, 26); tf_round(x0, x1, 6);
    x0 += ks1; x1 += ks2 + 1u;
    tf_round(x0, x1, 17); tf_round(x0, x1, 29); tf_round(x0, x1, 16); tf_round(x0, x1, 24);
    x0 += ks2; x1 += ks0 + 2u;
    tf_round(x0, x1, 13); tf_round(x0, x1, 15); tf_round(x0, x1, 26); tf_round(x0, x1, 6);
    x0 += ks0; x1 += ks1 + 3u;
    tf_round(x0, x1, 17); tf_round(x0, x1, 29); tf_round(x0, x1, 16); tf_round(x0, x1, 24);
    x0 += ks1; x1 += ks2 + 4u;
    tf_round(x0, x1, 13); tf_round(x0, x1, 15); tf_round(x0, x1, 26); tf_round(x0, x1, 6);
    x0 += ks2; x1 += ks0 + 5u;
    return make_uint2(x0, x1);
}

// ---------------------------------------------------------------------------
// Kernel: zero routing counters
// ---------------------------------------------------------------------------
__global__ void zero_counts_kernel() {
    if (threadIdx.x < N_EXPERTS) d_counts[threadIdx.x] = 0;
}

// ---------------------------------------------------------------------------
// Kernel: weight convert fp32 [K][N] -> fp16 transposed [N][K], batched z
// grid (N/32, K/32, nmat), block (32, 8)
// ---------------------------------------------------------------------------
__global__ __launch_bounds__(256)
void convT_kernel(const float* __restrict__ src, __half* __restrict__ dst,
                  int K, int N) {
    __shared__ float tile[32][33];
    long mat = blockIdx.z;
    const float* s = src + mat * (long)K * N;
    __half* d = dst + mat * (long)K * N;
    int n0 = blockIdx.x * 32, k0 = blockIdx.y * 32;
    int tx = threadIdx.x, ty = threadIdx.y;
    #pragma unroll
    for (int j = 0; j < 4; j++)
        tile[ty + 8 * j][tx] = s[(long)(k0 + ty + 8 * j) * N + n0 + tx];
    __syncthreads();
    #pragma unroll
    for (int j = 0; j < 4; j++)
        d[(long)(n0 + ty + 8 * j) * K + k0 + tx] = __float2half(tile[tx][ty + 8 * j]);
}

// ---------------------------------------------------------------------------
// Kernel: policy head + Gumbel top-2 routing.  One block per token.
// ---------------------------------------------------------------------------
__global__ __launch_bounds__(256)
void routing_kernel(const float* __restrict__ x,
                    const float* __restrict__ pw1, const float* __restrict__ pb1,
                    const float* __restrict__ pg1, const float* __restrict__ pbb1,
                    const float* __restrict__ pw2, const float* __restrict__ pb2) {
    __shared__ float xs[D_MODEL];
    __shared__ float red[256];
    __shared__ float gbuf[D_HALF];
    __shared__ float scores[N_EXPERTS];

    int token = blockIdx.x;
    int t = threadIdx.x;

    for (int i = t; i < D_MODEL; i += 256) xs[i] = x[(size_t)token * D_MODEL + i];
    __syncthreads();

    float acc = pb1[t];
    #pragma unroll 4
    for (int k = 0; k < D_MODEL; k++)
        acc = fmaf(xs[k], pw1[k * D_HALF + t], acc);

    float mean = reduce256(acc, red) * (1.0f / D_HALF);
    float d = acc - mean;
    float var = reduce256(d * d, red) * (1.0f / D_HALF);
    float hn = d * rsqrtf(var + 1e-5f) * pg1[t] + pbb1[t];
    gbuf[t] = gelu_f(hn);
    __syncthreads();

    if (t < N_EXPERTS) {
        float lg = pb2[t];
        #pragma unroll 4
        for (int j = 0; j < D_HALF; j++)
            lg = fmaf(gbuf[j], pw2[j * N_EXPERTS + t], lg);

        // partitionable threefry: counter (0, i), bits = out0 ^ out1
        uint32_t idx = (uint32_t)(token * N_EXPERTS + t);
        uint2 r = threefry2x32(0u, 42u, 0u, idx);
        uint32_t bits = r.x ^ r.y;
        float u = __uint_as_float((bits >> 9) | 0x3f800000u) - 1.0f;
        float gn = -logf(-logf(u + 1e-10f) + 1e-10f);
        scores[t] = lg + gn;
    }
    __syncthreads();

    if (t == 0) {
        int e1 = 0; float v1 = scores[0];
        #pragma unroll
        for (int e = 1; e < N_EXPERTS; e++)
            if (scores[e] > v1) { v1 = scores[e]; e1 = e; }
        int e2 = -1; float v2 = -1e30f;
        #pragma unroll
        for (int e = 0; e < N_EXPERTS; e++) {
            if (e == e1) continue;
            if (scores[e] > v2) { v2 = scores[e]; e2 = e; }
        }
        int p = atomicAdd(&d_counts[e1], 1);
        d_tlist[e1 * CAP + p] = token;
        p = atomicAdd(&d_counts[e2], 1);
        d_tlist[e2 * CAP + p] = token;
    }
}

// ---------------------------------------------------------------------------
// Kernel: gather selected token rows, converting to fp16
// grid (CAP, N_EXPERTS), 128 threads
// ---------------------------------------------------------------------------
__global__ void gather_kernel(const float* __restrict__ x) {
    int m = blockIdx.x, e = blockIdx.y;
    if (m >= d_counts[e]) return;
    int token = d_tlist[e * CAP + m];
    const float4* src = (const float4*)(x + (size_t)token * D_MODEL);
    __half2* dst = (__half2*)(d_Xg16 + ((size_t)e * CAP + m) * D_MODEL);
    float4 v = src[threadIdx.x];
    dst[2 * threadIdx.x]     = __floats2half2_rn(v.x, v.y);
    dst[2 * threadIdx.x + 1] = __floats2half2_rn(v.z, v.w);
}

// ---------------------------------------------------------------------------
// fp16 tensor-core GEMM, cp.async 2-stage ping-pong:
//   C[e] = act(A[e] @ BT[e]^T + bias[e])
//   A: [M_e,K] fp16 row-major; BT: [N,K] fp16 (k-contiguous).
// Tile 128x128xBK64; 8 warps 4(m)x2(n); warp 32x64 = 2x8 m16n8k16 per kstep.
// Outputs: optional fp32 C and/or fp16 C16.
// grid (N/128, CAP/128, N_EXPERTS), 256 threads, dyn smem = GEMM_SMEM.
// ---------------------------------------------------------------------------
template<int ACT, bool WF32, bool WF16>
__global__ __launch_bounds__(256, 2)
void gemm_h(const __half* __restrict__ Aall, long strideA,
            const __half* __restrict__ Btall, long strideB,
            const float* __restrict__ biasAll, long strideBias,
            float* __restrict__ Cfall, __half* __restrict__ Chall, long strideC,
            int N, int K) {
    extern __shared__ __align__(16) uint16_t smh[];

    int e = blockIdx.z;
    int M = d_counts[e];
    int m0 = blockIdx.y * 128;
    if (m0 >= M) return;
    int n0 = blockIdx.x * 128;

    const __half* A  = Aall  + (long)e * strideA;
    const __half* Bt = Btall + (long)e * strideB;
    const float* bias = biasAll + (long)e * strideBias;
    float*  Cf = WF32 ? Cfall + (long)e * strideC : nullptr;
    __half* Ch = WF16 ? Chall + (long)e * strideC : nullptr;

    int tid  = threadIdx.x;
    int wid  = tid >> 5;
    int lane = tid & 31;
    int wm = wid >> 1;            // 0..3  (m)
    int wn = wid & 1;             // 0..1  (n)
    int gid = lane >> 2;          // 0..7
    int tig = lane & 3;           // 0..3

    float acc[2][8][4];
    #pragma unroll
    for (int i = 0; i < 2; i++)
        #pragma unroll
        for (int j = 0; j < 8; j++)
            #pragma unroll
            for (int c = 0; c < 4; c++) acc[i][j][c] = 0.0f;

    const int NC = K >> 6;   // BK = 64

    auto load_tile = [&](int chunk) {
        uint16_t* As = smh + (chunk & 1) * STAGE_H;
        uint16_t* Bs = As + A_HALVES;
        int k0 = chunk << 6;
        #pragma unroll
        for (int i = 0; i < 4; i++) {
            int idx = i * 256 + tid;
            int r = idx >> 3, seg = idx & 7;     // 8 x 16B per 64-half row
            int rr = m0 + r;
            int sz = (rr < M) ? 16 : 0;
            int rc = (rr < M) ? rr : 0;
            cp16(smem_u32(&As[r * AS_ST + seg * 8]),
                 &A[(long)rc * K + k0 + seg * 8], sz);
        }
        #pragma unroll
        for (int i = 0; i < 4; i++) {
            int idx = i * 256 + tid;
            int r = idx >> 3, seg = idx & 7;
            cp16f(smem_u32(&Bs[r * AS_ST + seg * 8]),
                  &Bt[(long)(n0 + r) * K + k0 + seg * 8]);
        }
        cp_commit();
    };

    load_tile(0);

    for (int chunk = 0; chunk < NC; chunk++) {
        if (chunk + 1 < NC) { load_tile(chunk + 1); cp_wait<1>(); }
        else                { cp_wait<0>(); }
        __syncthreads();

        const uint16_t* As = smh + (chunk & 1) * STAGE_H;
        const uint16_t* Bs = As + A_HALVES;

        #pragma unroll
        for (int ks = 0; ks < 4; ks++) {
            int kk = ks * 16;
            uint32_t a[2][4];
            #pragma unroll
            for (int mt = 0; mt < 2; mt++) {
                int row = wm * 32 + mt * 16 + gid;
                const uint16_t* ap = &As[row * AS_ST + kk + 2 * tig];
                a[mt][0] = *(const uint32_t*)(ap);
                a[mt][1] = *(const uint32_t*)(ap + 8 * AS_ST);
                a[mt][2] = *(const uint32_t*)(ap + 8);
                a[mt][3] = *(const uint32_t*)(ap + 8 * AS_ST + 8);
            }
            #pragma unroll
            for (int nt = 0; nt < 8; nt++) {
                int col = wn * 64 + nt * 8 + gid;
                const uint16_t* bp = &Bs[col * AS_ST + kk + 2 * tig];
                uint32_t b[2];
                b[0] = *(const uint32_t*)(bp);
                b[1] = *(const uint32_t*)(bp + 8);
                mma_f16_16n8k16(acc[0][nt], a[0], b);
                mma_f16_16n8k16(acc[1][nt], a[1], b);
            }
        }
        __syncthreads();
    }

    // epilogue: bias + act; fp32 and/or fp16 stores
    #pragma unroll
    for (int mt = 0; mt < 2; mt++) {
        #pragma unroll
        for (int nt = 0; nt < 8; nt++) {
            int col = n0 + wn * 64 + nt * 8 + 2 * tig;
            float b0 = bias[col], b1 = bias[col + 1];
            int r0 = m0 + wm * 32 + mt * 16 + gid;
            int r1 = r0 + 8;
            float v0 = acc[mt][nt][0] + b0;
            float v1 = acc[mt][nt][1] + b1;
            float v2 = acc[mt][nt][2] + b0;
            float v3 = acc[mt][nt][3] + b1;
            if (ACT == 1) {
                v0 = gelu_f(v0); v1 = gelu_f(v1);
                v2 = gelu_f(v2); v3 = gelu_f(v3);
            }
            if (r0 < M) {
                if (WF32) *(float2*)&Cf[(long)r0 * N + col] = make_float2(v0, v1);
                if (WF16) *(__half2*)&Ch[(long)r0 * N + col] = __floats2half2_rn(v0, v1);
            }
            if (r1 < M) {
                if (WF32) *(float2*)&Cf[(long)r1 * N + col] = make_float2(v2, v3);
                if (WF16) *(__half2*)&Ch[(long)r1 * N + col] = __floats2half2_rn(v2, v3);
            }
        }
    }
}

// ---------------------------------------------------------------------------
// Kernel: per-row LN of h2, sigmoid gate from h, residual update (+fp16 mirror)
// ---------------------------------------------------------------------------
__global__ __launch_bounds__(256)
void lngate_kernel(const float* __restrict__ ng, const float* __restrict__ nb,
                   const float* __restrict__ gwv) {
    __shared__ float red[256];
    int m = blockIdx.x, e = blockIdx.y;
    if (m >= d_counts[e]) return;
    int t = threadIdx.x;

    float* h = d_H + ((size_t)e * CAP + m) * D_FF;
    __half* h16 = d_H16 + ((size_t)e * CAP + m) * D_FF;
    const float* h2 = d_H2 + ((size_t)e * CAP + m) * D_FF;
    const float* ng_e = ng + (size_t)e * (N_LAYERS * D_FF);
    const float* nb_e = nb + (size_t)e * (N_LAYERS * D_FF);
    const float* gw_e = gwv + (size_t)e * (N_LAYERS * D_FF);

    float hv[4], h2v[4];
    float s = 0.f, sq = 0.f, dot = 0.f;
    #pragma unroll
    for (int c = 0; c < 4; c++) {
        int i = t + c * 256;
        hv[c] = h[i];
        h2v[c] = h2[i];
        s += h2v[c];
        dot = fmaf(hv[c], gw_e[i], dot);
    }
    float mean = reduce256(s, red) * (1.0f / D_FF);
    #pragma unroll
    for (int c = 0; c < 4; c++) { float d = h2v[c] - mean; sq += d * d; }
    float var = reduce256(sq, red) * (1.0f / D_FF);
    float dtot = reduce256(dot, red);
    float gate = 1.0f / (1.0f + expf(-dtot));
    float rstd = rsqrtf(var + 1e-5f);

    #pragma unroll
    for (int c = 0; c < 4; c++) {
        int i = t + c * 256;
        float hn = (h2v[c] - mean) * rstd * ng_e[i] + nb_e[i];
        float nv = hv[c] + gate * hn;
        h[i] = nv;
        h16[i] = __float2half(nv);
    }
}

// ---------------------------------------------------------------------------
// Kernel: final residual LN + scatter-add into output.
// ---------------------------------------------------------------------------
__global__ __launch_bounds__(256)
void final_kernel(const float* __restrict__ x,
                  const float* __restrict__ fng, const float* __restrict__ fnb,
                  float* __restrict__ out) {
    __shared__ float red[256];
    int m = blockIdx.x, e = blockIdx.y;
    if (m >= d_counts[e]) return;
    int t = threadIdx.x;
    int token = d_tlist[e * CAP + m];

    const float* orow = d_Ob + ((size_t)e * CAP + m) * D_MODEL;
    const float* xrow = x + (size_t)token * D_MODEL;
    const float* g = fng + (size_t)e * D_MODEL;
    const float* b = fnb + (size_t)e * D_MODEL;

    float v[2];
    float s = 0.f, sq = 0.f;
    #pragma unroll
    for (int c = 0; c < 2; c++) {
        int i = t + c * 256;
        v[c] = xrow[i] + orow[i];
        s += v[c];
    }
    float mean = reduce256(s, red) * (1.0f / D_MODEL);
    #pragma unroll
    for (int c = 0; c < 2; c++) { float d = v[c] - mean; sq += d * d; }
    float var = reduce256(sq, red) * (1.0f / D_MODEL);
    float rstd = rsqrtf(var + 1e-5f);

    #pragma unroll
    for (int c = 0; c < 2; c++) {
        int i = t + c * 256;
        float y = (v[c] - mean) * rstd * g[i] + b[i];
        atomicAdd(&out[(size_t)token * D_MODEL + i], y);
    }
}

// ---------------------------------------------------------------------------
// Launch
// ---------------------------------------------------------------------------
extern "C" void kernel_launch(void* const* d_in, const int* in_sizes, int n_in,
                              void* d_out, int out_size) {
    const float* x    = (const float*)d_in[0];
    const float* pw1  = (const float*)d_in[1];
    const float* pb1  = (const float*)d_in[2];
    const float* pg1  = (const float*)d_in[3];
    const float* pbb1 = (const float*)d_in[4];
    const float* pw2  = (const float*)d_in[5];
    const float* pb2  = (const float*)d_in[6];
    const float* Win  = (const float*)d_in[7];
    const float* b_in = (const float*)d_in[8];
    const float* W1   = (const float*)d_in[9];
    const float* b1   = (const float*)d_in[10];
    const float* W2   = (const float*)d_in[11];
    const float* b2   = (const float*)d_in[12];
    const float* ng   = (const float*)d_in[13];
    const float* nb   = (const float*)d_in[14];
    const float* gw   = (const float*)d_in[15];
    const float* Wout = (const float*)d_in[16];
    const float* bout = (const float*)d_in[17];
    const float* fng  = (const float*)d_in[18];
    const float* fnb  = (const float*)d_in[19];
    float* out = (float*)d_out;

    __half *Xg16, *H16, *A216, *WinT, *W1T, *W2T, *WoutT;
    float *H, *H2, *Ob;
    cudaGetSymbolAddress((void**)&Xg16, d_Xg16);
    cudaGetSymbolAddress((void**)&H,    d_H);
    cudaGetSymbolAddress((void**)&H16,  d_H16);
    cudaGetSymbolAddress((void**)&A216, d_A216);
    cudaGetSymbolAddress((void**)&H2,   d_H2);
    cudaGetSymbolAddress((void**)&Ob,   d_Ob);
    cudaGetSymbolAddress((void**)&WinT,  d_WinT);
    cudaGetSymbolAddress((void**)&W1T,   d_W1T);
    cudaGetSymbolAddress((void**)&W2T,   d_W2T);
    cudaGetSymbolAddress((void**)&WoutT, d_WoutT);

    cudaFuncSetAttribute(gemm_h<0,true,true>,  cudaFuncAttributeMaxDynamicSharedMemorySize, GEMM_SMEM);
    cudaFuncSetAttribute(gemm_h<1,false,true>, cudaFuncAttributeMaxDynamicSharedMemorySize, GEMM_SMEM);
    cudaFuncSetAttribute(gemm_h<0,true,false>, cudaFuncAttributeMaxDynamicSharedMemorySize, GEMM_SMEM);

    cudaMemsetAsync(out, 0, (size_t)out_size * sizeof(float), 0);
    zero_counts_kernel<<<1, 32>>>();

    // one-time per-launch weight convert+transpose to fp16 [N][K]
    convT_kernel<<<dim3(D_FF / 32, D_MODEL / 32, N_EXPERTS), dim3(32, 8)>>>(
        Win, WinT, D_MODEL, D_FF);
    convT_kernel<<<dim3(D_FF2 / 32, D_FF / 32, N_EXPERTS * N_LAYERS), dim3(32, 8)>>>(
        W1, W1T, D_FF, D_FF2);
    convT_kernel<<<dim3(D_FF / 32, D_FF2 / 32, N_EXPERTS * N_LAYERS), dim3(32, 8)>>>(
        W2, W2T, D_FF2, D_FF);
    convT_kernel<<<dim3(D_MODEL / 32, D_FF / 32, N_EXPERTS), dim3(32, 8)>>>(
        Wout, WoutT, D_FF, D_MODEL);

    routing_kernel<<<N_TOKENS, 256>>>(x, pw1, pb1, pg1, pbb1, pw2, pb2);
    gather_kernel<<<dim3(CAP, N_EXPERTS), 128>>>(x);

    // H = Xg @ Win + b_in   -> fp32 H + fp16 H16
    gemm_h<0,true,true><<<dim3(D_FF / 128, CAP / 128, N_EXPERTS), 256, GEMM_SMEM>>>(
        Xg16, (long)CAP * D_MODEL,
        WinT, (long)D_FF * D_MODEL,
        b_in, (long)D_FF,
        H, H16, (long)CAP * D_FF,
        D_FF, D_MODEL);

    for (int l = 0; l < N_LAYERS; l++) {
        // A2 = gelu(H @ W1[l] + b1[l])  -> fp16 only
        gemm_h<1,false,true><<<dim3(D_FF2 / 128, CAP / 128, N_EXPERTS), 256, GEMM_SMEM>>>(
            H16, (long)CAP * D_FF,
            W1T + (long)l * D_FF2 * D_FF, (long)N_LAYERS * D_FF2 * D_FF,
            b1 + (long)l * D_FF2, (long)N_LAYERS * D_FF2,
            nullptr, A216, (long)CAP * D_FF2,
            D_FF2, D_FF);
        // H2 = A2 @ W2[l] + b2[l]  -> fp32 only
        gemm_h<0,true,false><<<dim3(D_FF / 128, CAP / 128, N_EXPERTS), 256, GEMM_SMEM>>>(
            A216, (long)CAP * D_FF2,
            W2T + (long)l * D_FF * D_FF2, (long)N_LAYERS * D_FF * D_FF2,
            b2 + (long)l * D_FF, (long)N_LAYERS * D_FF,
            H2, nullptr, (long)CAP * D_FF,
            D_FF, D_FF2);
        // H += sigmoid(H.gw) * LN(H2); refresh H16
        lngate_kernel<<<dim3(CAP, N_EXPERTS), 256>>>(
            ng + (long)l * D_FF, nb + (long)l * D_FF, gw + (long)l * D_FF);
    }

    // Ob = H @ Wout + bout  -> fp32 only
    gemm_h<0,true,false><<<dim3(D_MODEL / 128, CAP / 128, N_EXPERTS), 256, GEMM_SMEM>>>(
        H16, (long)CAP * D_FF,
        WoutT, (long)D_MODEL * D_FF,
        bout, (long)D_MODEL,
        Ob, nullptr, (long)CAP * D_MODEL,
        D_MODEL, D_FF);

    final_kernel<<<dim3(CAP, N_EXPERTS), 256>>>(x, fng, fnb, out);
}

// round 15
// speedup vs baseline: 2.0576x; 1.0276x over previous
#include <cuda_runtime.h>
#include <cuda_fp16.h>
#include <cstdint>

// ---------------------------------------------------------------------------
// Problem constants
// ---------------------------------------------------------------------------
#define D_MODEL   512
#define D_HALF    256
#define D_FF      1024
#define D_FF2     2048
#define N_LAYERS  2
#define N_EXPERTS 8
#define N_TOKENS  2048
#define CAP       2048

// fp16 GEMM smem staging: tile 128(M) x 128(N) x 64(K)
// A smem: [128 rows m][72 halves]   (64 data + 8 pad)  -> word stride 36 (≡4 mod 32)
// B smem: [64 rows k][136 halves]   (128 data + 8 pad) -> word stride 68 (≡4 mod 32)
#define AS_ST     72
#define BS_ST     136
#define A_HALVES  (128 * AS_ST)               // 9216
#define B_HALVES  (64 * BS_ST)                // 8704
#define STAGE_H   (A_HALVES + B_HALVES)       // 17920 halves
#define GEMM_SMEM (STAGE_H * 2 * 2)           // 71680 bytes -> 2 CTAs/SM

// ---------------------------------------------------------------------------
// Static scratch (no allocations allowed)
// ---------------------------------------------------------------------------
__device__ __half d_Xg16[(size_t)N_EXPERTS * CAP * D_MODEL];
__device__ float  d_H   [(size_t)N_EXPERTS * CAP * D_FF];
__device__ __half d_H16 [(size_t)N_EXPERTS * CAP * D_FF];
__device__ __half d_A216[(size_t)N_EXPERTS * CAP * D_FF2];
__device__ float  d_H2  [(size_t)N_EXPERTS * CAP * D_FF];
__device__ float  d_Ob  [(size_t)N_EXPERTS * CAP * D_MODEL];
__device__ int    d_counts[N_EXPERTS];
__device__ int    d_tlist[N_EXPERTS * CAP];
// fp16 weights, ORIGINAL layout [K][N] (no transpose)
__device__ __half d_Win16 [(size_t)N_EXPERTS * D_MODEL * D_FF];
__device__ __half d_W116  [(size_t)N_EXPERTS * N_LAYERS * D_FF * D_FF2];
__device__ __half d_W216  [(size_t)N_EXPERTS * N_LAYERS * D_FF2 * D_FF];
__device__ __half d_Wout16[(size_t)N_EXPERTS * D_FF * D_MODEL];

// ---------------------------------------------------------------------------
// Helpers
// ---------------------------------------------------------------------------
__device__ __forceinline__ float gelu_f(float v) {
    return 0.5f * v * (1.0f + erff(v * 0.70710678118654752440f));
}

__device__ __forceinline__ uint32_t smem_u32(const void* p) {
    uint32_t a;
    asm("{ .reg .u64 t; cvta.to.shared.u64 t, %1; cvt.u32.u64 %0, t; }" : "=r"(a) : "l"(p));
    return a;
}

__device__ __forceinline__ void cp16(uint32_t dst, const void* src, int szbytes) {
    asm volatile("cp.async.cg.shared.global [%0], [%1], 16, %2;"
                 :: "r"(dst), "l"(src), "r"(szbytes));
}
__device__ __forceinline__ void cp16f(uint32_t dst, const void* src) {
    asm volatile("cp.async.cg.shared.global [%0], [%1], 16;"
                 :: "r"(dst), "l"(src));
}
__device__ __forceinline__ void cp_commit() {
    asm volatile("cp.async.commit_group;" ::: "memory");
}
template<int N>
__device__ __forceinline__ void cp_wait() {
    asm volatile("cp.async.wait_group %0;" :: "n"(N) : "memory");
}

__device__ __forceinline__ void ldsm_x4(uint32_t* r, uint32_t addr) {
    asm volatile("ldmatrix.sync.aligned.m8n8.x4.shared.b16 {%0,%1,%2,%3}, [%4];"
                 : "=r"(r[0]), "=r"(r[1]), "=r"(r[2]), "=r"(r[3]) : "r"(addr));
}
__device__ __forceinline__ void ldsm_x4_trans(uint32_t* r, uint32_t addr) {
    asm volatile("ldmatrix.sync.aligned.m8n8.x4.trans.shared.b16 {%0,%1,%2,%3}, [%4];"
                 : "=r"(r[0]), "=r"(r[1]), "=r"(r[2]), "=r"(r[3]) : "r"(addr));
}

// m16n8k16 fp16 mma, fp32 accum
__device__ __forceinline__ void mma_f16_16n8k16(float* c, const uint32_t* a,
                                                const uint32_t* b) {
    asm volatile(
        "mma.sync.aligned.m16n8k16.row.col.f32.f16.f16.f32 "
        "{%0,%1,%2,%3}, {%4,%5,%6,%7}, {%8,%9}, {%0,%1,%2,%3};"
        : "+f"(c[0]), "+f"(c[1]), "+f"(c[2]), "+f"(c[3])
        : "r"(a[0]), "r"(a[1]), "r"(a[2]), "r"(a[3]), "r"(b[0]), "r"(b[1]));
}

__device__ __forceinline__ float reduce256(float v, float* red) {
    int t = threadIdx.x;
    red[t] = v;
    __syncthreads();
    #pragma unroll
    for (int s = 128; s > 0; s >>= 1) {
        if (t < s) red[t] += red[t + s];
        __syncthreads();
    }
    float r = red[0];
    __syncthreads();
    return r;
}

__device__ __forceinline__ void tf_round(uint32_t& a, uint32_t& b, int r) {
    a += b;
    b = (b << r) | (b >> (32 - r));
    b ^= a;
}

__device__ __forceinline__ uint2 threefry2x32(uint32_t k0, uint32_t k1,
                                              uint32_t x0, uint32_t x1) {
    uint32_t ks0 = k0, ks1 = k1, ks2 = k0 ^ k1 ^ 0x1BD11BDAu;
    x0 += ks0; x1 += ks1;
    tf_round(x0, x1, 13); tf_round(x0, x1, 15); tf_round(x0, x1, 26); tf_round(x0, x1, 6);
    x0 += ks1; x1 += ks2 + 1u;
    tf_round(x0, x1, 17); tf_round(x0, x1, 29); tf_round(x0, x1, 16); tf_round(x0, x1, 24);
    x0 += ks2; x1 += ks0 + 2u;
    tf_round(x0, x1, 13); tf_round(x0, x1, 15); tf_round(x0, x1, 26); tf_round(x0, x1, 6);
    x0 += ks0; x1 += ks1 + 3u;
    tf_round(x0, x1, 17); tf_round(x0, x1, 29); tf_round(x0, x1, 16); tf_round(x0, x1, 24);
    x0 += ks1; x1 += ks2 + 4u;
    tf_round(x0, x1, 13); tf_round(x0, x1, 15); tf_round(x0, x1, 26); tf_round(x0, x1, 6);
    x0 += ks2; x1 += ks0 + 5u;
    return make_uint2(x0, x1);
}

// ---------------------------------------------------------------------------
// Kernel: zero routing counters
// ---------------------------------------------------------------------------
__global__ void zero_counts_kernel() {
    if (threadIdx.x < N_EXPERTS) d_counts[threadIdx.x] = 0;
}

// ---------------------------------------------------------------------------
// Kernel: streaming fp32 -> fp16 convert (same layout, no transpose)
// one thread = one float4 -> one 8B half4 store
// ---------------------------------------------------------------------------
struct h4 { __half2 a, b; };
__global__ __launch_bounds__(256)
void conv_kernel(const float4* __restrict__ src, h4* __restrict__ dst, long n4) {
    long i = (long)blockIdx.x * 256 + threadIdx.x;
    if (i < n4) {
        float4 v = src[i];
        h4 o;
        o.a = __floats2half2_rn(v.x, v.y);
        o.b = __floats2half2_rn(v.z, v.w);
        dst[i] = o;
    }
}

// ---------------------------------------------------------------------------
// Kernel: policy head + Gumbel top-2 routing.  One block per token.
// ---------------------------------------------------------------------------
__global__ __launch_bounds__(256)
void routing_kernel(const float* __restrict__ x,
                    const float* __restrict__ pw1, const float* __restrict__ pb1,
                    const float* __restrict__ pg1, const float* __restrict__ pbb1,
                    const float* __restrict__ pw2, const float* __restrict__ pb2) {
    __shared__ float xs[D_MODEL];
    __shared__ float red[256];
    __shared__ float gbuf[D_HALF];
    __shared__ float scores[N_EXPERTS];

    int token = blockIdx.x;
    int t = threadIdx.x;

    for (int i = t; i < D_MODEL; i += 256) xs[i] = x[(size_t)token * D_MODEL + i];
    __syncthreads();

    float acc = pb1[t];
    #pragma unroll 4
    for (int k = 0; k < D_MODEL; k++)
        acc = fmaf(xs[k], pw1[k * D_HALF + t], acc);

    float mean = reduce256(acc, red) * (1.0f / D_HALF);
    float d = acc - mean;
    float var = reduce256(d * d, red) * (1.0f / D_HALF);
    float hn = d * rsqrtf(var + 1e-5f) * pg1[t] + pbb1[t];
    gbuf[t] = gelu_f(hn);
    __syncthreads();

    if (t < N_EXPERTS) {
        float lg = pb2[t];
        #pragma unroll 4
        for (int j = 0; j < D_HALF; j++)
            lg = fmaf(gbuf[j], pw2[j * N_EXPERTS + t], lg);

        // partitionable threefry: counter (0, i), bits = out0 ^ out1
        uint32_t idx = (uint32_t)(token * N_EXPERTS + t);
        uint2 r = threefry2x32(0u, 42u, 0u, idx);
        uint32_t bits = r.x ^ r.y;
        float u = __uint_as_float((bits >> 9) | 0x3f800000u) - 1.0f;
        float gn = -logf(-logf(u + 1e-10f) + 1e-10f);
        scores[t] = lg + gn;
    }
    __syncthreads();

    if (t == 0) {
        int e1 = 0; float v1 = scores[0];
        #pragma unroll
        for (int e = 1; e < N_EXPERTS; e++)
            if (scores[e] > v1) { v1 = scores[e]; e1 = e; }
        int e2 = -1; float v2 = -1e30f;
        #pragma unroll
        for (int e = 0; e < N_EXPERTS; e++) {
            if (e == e1) continue;
            if (scores[e] > v2) { v2 = scores[e]; e2 = e; }
        }
        int p = atomicAdd(&d_counts[e1], 1);
        d_tlist[e1 * CAP + p] = token;
        p = atomicAdd(&d_counts[e2], 1);
        d_tlist[e2 * CAP + p] = token;
    }
}

// ---------------------------------------------------------------------------
// Kernel: gather selected token rows, converting to fp16
// ---------------------------------------------------------------------------
__global__ void gather_kernel(const float* __restrict__ x) {
    int m = blockIdx.x, e = blockIdx.y;
    if (m >= d_counts[e]) return;
    int token = d_tlist[e * CAP + m];
    const float4* src = (const float4*)(x + (size_t)token * D_MODEL);
    __half2* dst = (__half2*)(d_Xg16 + ((size_t)e * CAP + m) * D_MODEL);
    float4 v = src[threadIdx.x];
    dst[2 * threadIdx.x]     = __floats2half2_rn(v.x, v.y);
    dst[2 * threadIdx.x + 1] = __floats2half2_rn(v.z, v.w);
}

// ---------------------------------------------------------------------------
// fp16 tensor-core GEMM, cp.async 2-stage ping-pong, ldmatrix fragments:
//   C[e] = act(A[e] @ B[e] + bias[e])
//   A: [M_e,K] fp16 row-major; B: [K,N] fp16 row-major (ORIGINAL layout).
// Tile 128x128x64; 8 warps 4(m)x2(n); warp 32x64 = 2x8 m16n8k16 per kstep.
// A frags: ldmatrix.x4 (2/kstep). B frags: ldmatrix.x4.trans (4/kstep).
// grid (N/128, CAP/128, N_EXPERTS), 256 threads, dyn smem = GEMM_SMEM.
// ---------------------------------------------------------------------------
template<int ACT, bool WF32, bool WF16>
__global__ __launch_bounds__(256, 2)
void gemm_h(const __half* __restrict__ Aall, long strideA,
            const __half* __restrict__ Ball, long strideB,
            const float* __restrict__ biasAll, long strideBias,
            float* __restrict__ Cfall, __half* __restrict__ Chall, long strideC,
            int N, int K) {
    extern __shared__ __align__(16) uint16_t smh[];

    int e = blockIdx.z;
    int M = d_counts[e];
    int m0 = blockIdx.y * 128;
    if (m0 >= M) return;
    int n0 = blockIdx.x * 128;

    const __half* A = Aall + (long)e * strideA;
    const __half* B = Ball + (long)e * strideB;
    const float* bias = biasAll + (long)e * strideBias;
    float*  Cf = WF32 ? Cfall + (long)e * strideC : nullptr;
    __half* Ch = WF16 ? Chall + (long)e * strideC : nullptr;

    int tid  = threadIdx.x;
    int wid  = tid >> 5;
    int lane = tid & 31;
    int wm = wid >> 1;            // 0..3  (m)
    int wn = wid & 1;             // 0..1  (n)
    int gid = lane >> 2;          // 0..7
    int tig = lane & 3;           // 0..3

    // ldmatrix per-lane row/col offsets (same pattern for A and B)
    int lrow = (lane & 7) + 8 * ((lane >> 3) & 1);   // row within 16
    int lcol = 8 * (lane >> 4);                      // 0 or 8 (k off for A, n off for B)

    float acc[2][8][4];
    #pragma unroll
    for (int i = 0; i < 2; i++)
        #pragma unroll
        for (int j = 0; j < 8; j++)
            #pragma unroll
            for (int c = 0; c < 4; c++) acc[i][j][c] = 0.0f;

    const int NC = K >> 6;   // BK = 64

    auto load_tile = [&](int chunk) {
        uint16_t* As = smh + (chunk & 1) * STAGE_H;
        uint16_t* Bs = As + A_HALVES;
        int k0 = chunk << 6;
        // A: 128 rows x 64 halves = 8 segs of 8 halves per row
        #pragma unroll
        for (int i = 0; i < 4; i++) {
            int idx = i * 256 + tid;
            int r = idx >> 3, seg = idx & 7;
            int rr = m0 + r;
            int sz = (rr < M) ? 16 : 0;
            int rc = (rr < M) ? rr : 0;
            cp16(smem_u32(&As[r * AS_ST + seg * 8]),
                 &A[(long)rc * K + k0 + seg * 8], sz);
        }
        // B: 64 rows (k) x 128 halves (n) = 16 segs of 8 halves per row
        #pragma unroll
        for (int i = 0; i < 4; i++) {
            int idx = i * 256 + tid;
            int r = idx >> 4, seg = idx & 15;
            cp16f(smem_u32(&Bs[r * BS_ST + seg * 8]),
                  &B[(long)(k0 + r) * N + n0 + seg * 8]);
        }
        cp_commit();
    };

    load_tile(0);

    for (int chunk = 0; chunk < NC; chunk++) {
        if (chunk + 1 < NC) { load_tile(chunk + 1); cp_wait<1>(); }
        else                { cp_wait<0>(); }
        __syncthreads();

        const uint16_t* As = smh + (chunk & 1) * STAGE_H;
        const uint16_t* Bs = As + A_HALVES;
        // per-lane ldmatrix base addresses (bytes)
        uint32_t aBase = smem_u32(As) + (uint32_t)(((wm * 32 + lrow) * AS_ST + lcol) * 2);
        uint32_t bBase = smem_u32(Bs) + (uint32_t)((lrow * BS_ST + wn * 64 + lcol) * 2);

        #pragma unroll
        for (int ks = 0; ks < 4; ks++) {
            uint32_t a[2][4];
            #pragma unroll
            for (int mt = 0; mt < 2; mt++)
                ldsm_x4(a[mt], aBase + (uint32_t)((mt * 16 * AS_ST + ks * 16) * 2));

            uint32_t b[8][2];
            #pragma unroll
            for (int nb = 0; nb < 4; nb++) {
                uint32_t r[4];
                ldsm_x4_trans(r, bBase + (uint32_t)((ks * 16 * BS_ST + nb * 16) * 2));
                b[2 * nb][0]     = r[0];
                b[2 * nb][1]     = r[1];
                b[2 * nb + 1][0] = r[2];
                b[2 * nb + 1][1] = r[3];
            }
            #pragma unroll
            for (int nt = 0; nt < 8; nt++) {
                mma_f16_16n8k16(acc[0][nt], a[0], b[nt]);
                mma_f16_16n8k16(acc[1][nt], a[1], b[nt]);
            }
        }
        __syncthreads();
    }

    // epilogue: bias + act; fp32 and/or fp16 stores
    #pragma unroll
    for (int mt = 0; mt < 2; mt++) {
        #pragma unroll
        for (int nt = 0; nt < 8; nt++) {
            int col = n0 + wn * 64 + nt * 8 + 2 * tig;
            float b0 = bias[col], b1 = bias[col + 1];
            int r0 = m0 + wm * 32 + mt * 16 + gid;
            int r1 = r0 + 8;
            float v0 = acc[mt][nt][0] + b0;
            float v1 = acc[mt][nt][1] + b1;
            float v2 = acc[mt][nt][2] + b0;
            float v3 = acc[mt][nt][3] + b1;
            if (ACT == 1) {
                v0 = gelu_f(v0); v1 = gelu_f(v1);
                v2 = gelu_f(v2); v3 = gelu_f(v3);
            }
            if (r0 < M) {
                if (WF32) *(float2*)&Cf[(long)r0 * N + col] = make_float2(v0, v1);
                if (WF16) *(__half2*)&Ch[(long)r0 * N + col] = __floats2half2_rn(v0, v1);
            }
            if (r1 < M) {
                if (WF32) *(float2*)&Cf[(long)r1 * N + col] = make_float2(v2, v3);
                if (WF16) *(__half2*)&Ch[(long)r1 * N + col] = __floats2half2_rn(v2, v3);
            }
        }
    }
}

// ---------------------------------------------------------------------------
// Kernel: per-row LN of h2, sigmoid gate from h, residual update (+fp16 mirror)
// ---------------------------------------------------------------------------
__global__ __launch_bounds__(256)
void lngate_kernel(const float* __restrict__ ng, const float* __restrict__ nb,
                   const float* __restrict__ gwv) {
    __shared__ float red[256];
    int m = blockIdx.x, e = blockIdx.y;
    if (m >= d_counts[e]) return;
    int t = threadIdx.x;

    float* h = d_H + ((size_t)e * CAP + m) * D_FF;
    __half* h16 = d_H16 + ((size_t)e * CAP + m) * D_FF;
    const float* h2 = d_H2 + ((size_t)e * CAP + m) * D_FF;
    const float* ng_e = ng + (size_t)e * (N_LAYERS * D_FF);
    const float* nb_e = nb + (size_t)e * (N_LAYERS * D_FF);
    const float* gw_e = gwv + (size_t)e * (N_LAYERS * D_FF);

    float hv[4], h2v[4];
    float s = 0.f, sq = 0.f, dot = 0.f;
    #pragma unroll
    for (int c = 0; c < 4; c++) {
        int i = t + c * 256;
        hv[c] = h[i];
        h2v[c] = h2[i];
        s += h2v[c];
        dot = fmaf(hv[c], gw_e[i], dot);
    }
    float mean = reduce256(s, red) * (1.0f / D_FF);
    #pragma unroll
    for (int c = 0; c < 4; c++) { float d = h2v[c] - mean; sq += d * d; }
    float var = reduce256(sq, red) * (1.0f / D_FF);
    float dtot = reduce256(dot, red);
    float gate = 1.0f / (1.0f + expf(-dtot));
    float rstd = rsqrtf(var + 1e-5f);

    #pragma unroll
    for (int c = 0; c < 4; c++) {
        int i = t + c * 256;
        float hn = (h2v[c] - mean) * rstd * ng_e[i] + nb_e[i];
        float nv = hv[c] + gate * hn;
        h[i] = nv;
        h16[i] = __float2half(nv);
    }
}

// ---------------------------------------------------------------------------
// Kernel: final residual LN + scatter-add into output.
// ---------------------------------------------------------------------------
__global__ __launch_bounds__(256)
void final_kernel(const float* __restrict__ x,
                  const float* __restrict__ fng, const float* __restrict__ fnb,
                  float* __restrict__ out) {
    __shared__ float red[256];
    int m = blockIdx.x, e = blockIdx.y;
    if (m >= d_counts[e]) return;
    int t = threadIdx.x;
    int token = d_tlist[e * CAP + m];

    const float* orow = d_Ob + ((size_t)e * CAP + m) * D_MODEL;
    const float* xrow = x + (size_t)token * D_MODEL;
    const float* g = fng + (size_t)e * D_MODEL;
    const float* b = fnb + (size_t)e * D_MODEL;

    float v[2];
    float s = 0.f, sq = 0.f;
    #pragma unroll
    for (int c = 0; c < 2; c++) {
        int i = t + c * 256;
        v[c] = xrow[i] + orow[i];
        s += v[c];
    }
    float mean = reduce256(s, red) * (1.0f / D_MODEL);
    #pragma unroll
    for (int c = 0; c < 2; c++) { float d = v[c] - mean; sq += d * d; }
    float var = reduce256(sq, red) * (1.0f / D_MODEL);
    float rstd = rsqrtf(var + 1e-5f);

    #pragma unroll
    for (int c = 0; c < 2; c++) {
        int i = t + c * 256;
        float y = (v[c] - mean) * rstd * g[i] + b[i];
        atomicAdd(&out[(size_t)token * D_MODEL + i], y);
    }
}

// ---------------------------------------------------------------------------
// Launch
// ---------------------------------------------------------------------------
extern "C" void kernel_launch(void* const* d_in, const int* in_sizes, int n_in,
                              void* d_out, int out_size) {
    const float* x    = (const float*)d_in[0];
    const float* pw1  = (const float*)d_in[1];
    const float* pb1  = (const float*)d_in[2];
    const float* pg1  = (const float*)d_in[3];
    const float* pbb1 = (const float*)d_in[4];
    const float* pw2  = (const float*)d_in[5];
    const float* pb2  = (const float*)d_in[6];
    const float* Win  = (const float*)d_in[7];
    const float* b_in = (const float*)d_in[8];
    const float* W1   = (const float*)d_in[9];
    const float* b1   = (const float*)d_in[10];
    const float* W2   = (const float*)d_in[11];
    const float* b2   = (const float*)d_in[12];
    const float* ng   = (const float*)d_in[13];
    const float* nb   = (const float*)d_in[14];
    const float* gw   = (const float*)d_in[15];
    const float* Wout = (const float*)d_in[16];
    const float* bout = (const float*)d_in[17];
    const float* fng  = (const float*)d_in[18];
    const float* fnb  = (const float*)d_in[19];
    float* out = (float*)d_out;

    __half *Xg16, *H16, *A216, *Win16, *W116, *W216, *Wout16;
    float *H, *H2, *Ob;
    cudaGetSymbolAddress((void**)&Xg16, d_Xg16);
    cudaGetSymbolAddress((void**)&H,    d_H);
    cudaGetSymbolAddress((void**)&H16,  d_H16);
    cudaGetSymbolAddress((void**)&A216, d_A216);
    cudaGetSymbolAddress((void**)&H2,   d_H2);
    cudaGetSymbolAddress((void**)&Ob,   d_Ob);
    cudaGetSymbolAddress((void**)&Win16,  d_Win16);
    cudaGetSymbolAddress((void**)&W116,   d_W116);
    cudaGetSymbolAddress((void**)&W216,   d_W216);
    cudaGetSymbolAddress((void**)&Wout16, d_Wout16);

    cudaFuncSetAttribute(gemm_h<0,true,true>,  cudaFuncAttributeMaxDynamicSharedMemorySize, GEMM_SMEM);
    cudaFuncSetAttribute(gemm_h<1,false,true>, cudaFuncAttributeMaxDynamicSharedMemorySize, GEMM_SMEM);
    cudaFuncSetAttribute(gemm_h<0,true,false>, cudaFuncAttributeMaxDynamicSharedMemorySize, GEMM_SMEM);

    cudaMemsetAsync(out, 0, (size_t)out_size * sizeof(float), 0);
    zero_counts_kernel<<<1, 32>>>();

    // streaming fp32->fp16 weight conversion (same layout, no transpose)
    {
        long n;
        n = (long)N_EXPERTS * D_MODEL * D_FF / 4;
        conv_kernel<<<(unsigned)((n + 255) / 256), 256>>>((const float4*)Win, (h4*)Win16, n);
        n = (long)N_EXPERTS * N_LAYERS * D_FF * D_FF2 / 4;
        conv_kernel<<<(unsigned)((n + 255) / 256), 256>>>((const float4*)W1, (h4*)W116, n);
        n = (long)N_EXPERTS * N_LAYERS * D_FF2 * D_FF / 4;
        conv_kernel<<<(unsigned)((n + 255) / 256), 256>>>((const float4*)W2, (h4*)W216, n);
        n = (long)N_EXPERTS * D_FF * D_MODEL / 4;
        conv_kernel<<<(unsigned)((n + 255) / 256), 256>>>((const float4*)Wout, (h4*)Wout16, n);
    }

    routing_kernel<<<N_TOKENS, 256>>>(x, pw1, pb1, pg1, pbb1, pw2, pb2);
    gather_kernel<<<dim3(CAP, N_EXPERTS), 128>>>(x);

    // H = Xg @ Win + b_in   -> fp32 H + fp16 H16
    gemm_h<0,true,true><<<dim3(D_FF / 128, CAP / 128, N_EXPERTS), 256, GEMM_SMEM>>>(
        Xg16, (long)CAP * D_MODEL,
        Win16, (long)D_MODEL * D_FF,
        b_in, (long)D_FF,
        H, H16, (long)CAP * D_FF,
        D_FF, D_MODEL);

    for (int l = 0; l < N_LAYERS; l++) {
        // A2 = gelu(H @ W1[l] + b1[l])  -> fp16 only
        gemm_h<1,false,true><<<dim3(D_FF2 / 128, CAP / 128, N_EXPERTS), 256, GEMM_SMEM>>>(
            H16, (long)CAP * D_FF,
            W116 + (long)l * D_FF * D_FF2, (long)N_LAYERS * D_FF * D_FF2,
            b1 + (long)l * D_FF2, (long)N_LAYERS * D_FF2,
            nullptr, A216, (long)CAP * D_FF2,
            D_FF2, D_FF);
        // H2 = A2 @ W2[l] + b2[l]  -> fp32 only
        gemm_h<0,true,false><<<dim3(D_FF / 128, CAP / 128, N_EXPERTS), 256, GEMM_SMEM>>>(
            A216, (long)CAP * D_FF2,
            W216 + (long)l * D_FF2 * D_FF, (long)N_LAYERS * D_FF2 * D_FF,
            b2 + (long)l * D_FF, (long)N_LAYERS * D_FF,
            H2, nullptr, (long)CAP * D_FF,
            D_FF, D_FF2);
        // H += sigmoid(H.gw) * LN(H2); refresh H16
        lngate_kernel<<<dim3(CAP, N_EXPERTS), 256>>>(
            ng + (long)l * D_FF, nb + (long)l * D_FF, gw + (long)l * D_FF);
    }

    // Ob = H @ Wout + bout  -> fp32 only
    gemm_h<0,true,false><<<dim3(D_MODEL / 128, CAP / 128, N_EXPERTS), 256, GEMM_SMEM>>>(
        H16, (long)CAP * D_FF,
        Wout16, (long)D_FF * D_MODEL,
        bout, (long)D_MODEL,
        Ob, nullptr, (long)CAP * D_MODEL,
        D_MODEL, D_FF);

    final_kernel<<<dim3(CAP, N_EXPERTS), 256>>>(x, fng, fnb, out);
}

// round 16
// speedup vs baseline: 2.0642x; 1.0032x over previous
#include <cuda_runtime.h>
#include <cuda_fp16.h>
#include <cstdint>

// ---------------------------------------------------------------------------
// Problem constants
// ---------------------------------------------------------------------------
#define D_MODEL   512
#define D_HALF    256
#define D_FF      1024
#define D_FF2     2048
#define N_LAYERS  2
#define N_EXPERTS 8
#define N_TOKENS  2048
#define CAP       2048

// fp16 GEMM smem staging: tile 128(M) x 128(N) x 64(K)
#define AS_ST     72
#define BS_ST     136
#define A_HALVES  (128 * AS_ST)               // 9216
#define B_HALVES  (64 * BS_ST)                // 8704
#define STAGE_H   (A_HALVES + B_HALVES)       // 17920 halves
#define GEMM_SMEM (STAGE_H * 2 * 2)           // 71680 bytes -> 2 CTAs/SM

// ---------------------------------------------------------------------------
// Static scratch (no allocations allowed)
// ---------------------------------------------------------------------------
__device__ __half d_Xg16[(size_t)N_EXPERTS * CAP * D_MODEL];
__device__ float  d_H   [(size_t)N_EXPERTS * CAP * D_FF];
__device__ __half d_H16 [(size_t)N_EXPERTS * CAP * D_FF];
__device__ __half d_A216[(size_t)N_EXPERTS * CAP * D_FF2];
__device__ float  d_H2  [(size_t)N_EXPERTS * CAP * D_FF];
__device__ float  d_Ob  [(size_t)N_EXPERTS * CAP * D_MODEL];
__device__ int    d_counts[N_EXPERTS];
__device__ int    d_tlist[N_EXPERTS * CAP];
// fp16 weights, ORIGINAL layout [K][N] (no transpose)
__device__ __half d_Win16 [(size_t)N_EXPERTS * D_MODEL * D_FF];
__device__ __half d_W116  [(size_t)N_EXPERTS * N_LAYERS * D_FF * D_FF2];
__device__ __half d_W216  [(size_t)N_EXPERTS * N_LAYERS * D_FF2 * D_FF];
__device__ __half d_Wout16[(size_t)N_EXPERTS * D_FF * D_MODEL];

// ---------------------------------------------------------------------------
// Helpers
// ---------------------------------------------------------------------------
__device__ __forceinline__ float gelu_f(float v) {
    return 0.5f * v * (1.0f + erff(v * 0.70710678118654752440f));
}

__device__ __forceinline__ uint32_t smem_u32(const void* p) {
    uint32_t a;
    asm("{ .reg .u64 t; cvta.to.shared.u64 t, %1; cvt.u32.u64 %0, t; }" : "=r"(a) : "l"(p));
    return a;
}

__device__ __forceinline__ void cp16(uint32_t dst, const void* src, int szbytes) {
    asm volatile("cp.async.cg.shared.global [%0], [%1], 16, %2;"
                 :: "r"(dst), "l"(src), "r"(szbytes));
}
__device__ __forceinline__ void cp16f(uint32_t dst, const void* src) {
    asm volatile("cp.async.cg.shared.global [%0], [%1], 16;"
                 :: "r"(dst), "l"(src));
}
__device__ __forceinline__ void cp_commit() {
    asm volatile("cp.async.commit_group;" ::: "memory");
}
template<int N>
__device__ __forceinline__ void cp_wait() {
    asm volatile("cp.async.wait_group %0;" :: "n"(N) : "memory");
}

__device__ __forceinline__ void ldsm_x4(uint32_t* r, uint32_t addr) {
    asm volatile("ldmatrix.sync.aligned.m8n8.x4.shared.b16 {%0,%1,%2,%3}, [%4];"
                 : "=r"(r[0]), "=r"(r[1]), "=r"(r[2]), "=r"(r[3]) : "r"(addr));
}
__device__ __forceinline__ void ldsm_x4_trans(uint32_t* r, uint32_t addr) {
    asm volatile("ldmatrix.sync.aligned.m8n8.x4.trans.shared.b16 {%0,%1,%2,%3}, [%4];"
                 : "=r"(r[0]), "=r"(r[1]), "=r"(r[2]), "=r"(r[3]) : "r"(addr));
}

// m16n8k16 fp16 mma, fp32 accum
__device__ __forceinline__ void mma_f16_16n8k16(float* c, const uint32_t* a,
                                                const uint32_t* b) {
    asm volatile(
        "mma.sync.aligned.m16n8k16.row.col.f32.f16.f16.f32 "
        "{%0,%1,%2,%3}, {%4,%5,%6,%7}, {%8,%9}, {%0,%1,%2,%3};"
        : "+f"(c[0]), "+f"(c[1]), "+f"(c[2]), "+f"(c[3])
        : "r"(a[0]), "r"(a[1]), "r"(a[2]), "r"(a[3]), "r"(b[0]), "r"(b[1]));
}

__device__ __forceinline__ float reduce256(float v, float* red) {
    int t = threadIdx.x;
    red[t] = v;
    __syncthreads();
    #pragma unroll
    for (int s = 128; s > 0; s >>= 1) {
        if (t < s) red[t] += red[t + s];
        __syncthreads();
    }
    float r = red[0];
    __syncthreads();
    return r;
}

__device__ __forceinline__ void tf_round(uint32_t& a, uint32_t& b, int r) {
    a += b;
    b = (b << r) | (b >> (32 - r));
    b ^= a;
}

__device__ __forceinline__ uint2 threefry2x32(uint32_t k0, uint32_t k1,
                                              uint32_t x0, uint32_t x1) {
    uint32_t ks0 = k0, ks1 = k1, ks2 = k0 ^ k1 ^ 0x1BD11BDAu;
    x0 += ks0; x1 += ks1;
    tf_round(x0, x1, 13); tf_round(x0, x1, 15); tf_round(x0, x1, 26); tf_round(x0, x1, 6);
    x0 += ks1; x1 += ks2 + 1u;
    tf_round(x0, x1, 17); tf_round(x0, x1, 29); tf_round(x0, x1, 16); tf_round(x0, x1, 24);
    x0 += ks2; x1 += ks0 + 2u;
    tf_round(x0, x1, 13); tf_round(x0, x1, 15); tf_round(x0, x1, 26); tf_round(x0, x1, 6);
    x0 += ks0; x1 += ks1 + 3u;
    tf_round(x0, x1, 17); tf_round(x0, x1, 29); tf_round(x0, x1, 16); tf_round(x0, x1, 24);
    x0 += ks1; x1 += ks2 + 4u;
    tf_round(x0, x1, 13); tf_round(x0, x1, 15); tf_round(x0, x1, 26); tf_round(x0, x1, 6);
    x0 += ks2; x1 += ks0 + 5u;
    return make_uint2(x0, x1);
}

// ---------------------------------------------------------------------------
// Kernel: zero routing counters
// ---------------------------------------------------------------------------
__global__ void zero_counts_kernel() {
    if (threadIdx.x < N_EXPERTS) d_counts[threadIdx.x] = 0;
}

// ---------------------------------------------------------------------------
// Kernel: streaming fp32 -> fp16 convert (same layout, no transpose)
// ---------------------------------------------------------------------------
struct h4 { __half2 a, b; };
__global__ __launch_bounds__(256)
void conv_kernel(const float4* __restrict__ src, h4* __restrict__ dst, long n4) {
    long i = (long)blockIdx.x * 256 + threadIdx.x;
    if (i < n4) {
        float4 v = src[i];
        h4 o;
        o.a = __floats2half2_rn(v.x, v.y);
        o.b = __floats2half2_rn(v.z, v.w);
        dst[i] = o;
    }
}

// ---------------------------------------------------------------------------
// Kernel: policy head + Gumbel top-2 routing.  One block per token.
// ---------------------------------------------------------------------------
__global__ __launch_bounds__(256)
void routing_kernel(const float* __restrict__ x,
                    const float* __restrict__ pw1, const float* __restrict__ pb1,
                    const float* __restrict__ pg1, const float* __restrict__ pbb1,
                    const float* __restrict__ pw2, const float* __restrict__ pb2) {
    __shared__ float xs[D_MODEL];
    __shared__ float red[256];
    __shared__ float gbuf[D_HALF];
    __shared__ float scores[N_EXPERTS];

    int token = blockIdx.x;
    int t = threadIdx.x;

    for (int i = t; i < D_MODEL; i += 256) xs[i] = x[(size_t)token * D_MODEL + i];
    __syncthreads();

    float acc = pb1[t];
    #pragma unroll 4
    for (int k = 0; k < D_MODEL; k++)
        acc = fmaf(xs[k], pw1[k * D_HALF + t], acc);

    float mean = reduce256(acc, red) * (1.0f / D_HALF);
    float d = acc - mean;
    float var = reduce256(d * d, red) * (1.0f / D_HALF);
    float hn = d * rsqrtf(var + 1e-5f) * pg1[t] + pbb1[t];
    gbuf[t] = gelu_f(hn);
    __syncthreads();

    if (t < N_EXPERTS) {
        float lg = pb2[t];
        #pragma unroll 4
        for (int j = 0; j < D_HALF; j++)
            lg = fmaf(gbuf[j], pw2[j * N_EXPERTS + t], lg);

        // partitionable threefry: counter (0, i), bits = out0 ^ out1
        uint32_t idx = (uint32_t)(token * N_EXPERTS + t);
        uint2 r = threefry2x32(0u, 42u, 0u, idx);
        uint32_t bits = r.x ^ r.y;
        float u = __uint_as_float((bits >> 9) | 0x3f800000u) - 1.0f;
        float gn = -logf(-logf(u + 1e-10f) + 1e-10f);
        scores[t] = lg + gn;
    }
    __syncthreads();

    if (t == 0) {
        int e1 = 0; float v1 = scores[0];
        #pragma unroll
        for (int e = 1; e < N_EXPERTS; e++)
            if (scores[e] > v1) { v1 = scores[e]; e1 = e; }
        int e2 = -1; float v2 = -1e30f;
        #pragma unroll
        for (int e = 0; e < N_EXPERTS; e++) {
            if (e == e1) continue;
            if (scores[e] > v2) { v2 = scores[e]; e2 = e; }
        }
        int p = atomicAdd(&d_counts[e1], 1);
        d_tlist[e1 * CAP + p] = token;
        p = atomicAdd(&d_counts[e2], 1);
        d_tlist[e2 * CAP + p] = token;
    }
}

// ---------------------------------------------------------------------------
// Kernel: gather selected token rows, converting to fp16
// ---------------------------------------------------------------------------
__global__ void gather_kernel(const float* __restrict__ x) {
    int m = blockIdx.x, e = blockIdx.y;
    if (m >= d_counts[e]) return;
    int token = d_tlist[e * CAP + m];
    const float4* src = (const float4*)(x + (size_t)token * D_MODEL);
    __half2* dst = (__half2*)(d_Xg16 + ((size_t)e * CAP + m) * D_MODEL);
    float4 v = src[threadIdx.x];
    dst[2 * threadIdx.x]     = __floats2half2_rn(v.x, v.y);
    dst[2 * threadIdx.x + 1] = __floats2half2_rn(v.z, v.w);
}

// ---------------------------------------------------------------------------
// fp16 tensor-core GEMM, cp.async 2-stage ping-pong, ldmatrix fragments.
// (unchanged from R15 — proven best)
// ---------------------------------------------------------------------------
template<int ACT, bool WF32, bool WF16>
__global__ __launch_bounds__(256, 2)
void gemm_h(const __half* __restrict__ Aall, long strideA,
            const __half* __restrict__ Ball, long strideB,
            const float* __restrict__ biasAll, long strideBias,
            float* __restrict__ Cfall, __half* __restrict__ Chall, long strideC,
            int N, int K) {
    extern __shared__ __align__(16) uint16_t smh[];

    int e = blockIdx.z;
    int M = d_counts[e];
    int m0 = blockIdx.y * 128;
    if (m0 >= M) return;
    int n0 = blockIdx.x * 128;

    const __half* A = Aall + (long)e * strideA;
    const __half* B = Ball + (long)e * strideB;
    const float* bias = biasAll + (long)e * strideBias;
    float*  Cf = WF32 ? Cfall + (long)e * strideC : nullptr;
    __half* Ch = WF16 ? Chall + (long)e * strideC : nullptr;

    int tid  = threadIdx.x;
    int wid  = tid >> 5;
    int lane = tid & 31;
    int wm = wid >> 1;            // 0..3  (m)
    int wn = wid & 1;             // 0..1  (n)
    int gid = lane >> 2;          // 0..7
    int tig = lane & 3;           // 0..3

    int lrow = (lane & 7) + 8 * ((lane >> 3) & 1);
    int lcol = 8 * (lane >> 4);

    float acc[2][8][4];
    #pragma unroll
    for (int i = 0; i < 2; i++)
        #pragma unroll
        for (int j = 0; j < 8; j++)
            #pragma unroll
            for (int c = 0; c < 4; c++) acc[i][j][c] = 0.0f;

    const int NC = K >> 6;   // BK = 64

    auto load_tile = [&](int chunk) {
        uint16_t* As = smh + (chunk & 1) * STAGE_H;
        uint16_t* Bs = As + A_HALVES;
        int k0 = chunk << 6;
        #pragma unroll
        for (int i = 0; i < 4; i++) {
            int idx = i * 256 + tid;
            int r = idx >> 3, seg = idx & 7;
            int rr = m0 + r;
            int sz = (rr < M) ? 16 : 0;
            int rc = (rr < M) ? rr : 0;
            cp16(smem_u32(&As[r * AS_ST + seg * 8]),
                 &A[(long)rc * K + k0 + seg * 8], sz);
        }
        #pragma unroll
        for (int i = 0; i < 4; i++) {
            int idx = i * 256 + tid;
            int r = idx >> 4, seg = idx & 15;
            cp16f(smem_u32(&Bs[r * BS_ST + seg * 8]),
                  &B[(long)(k0 + r) * N + n0 + seg * 8]);
        }
        cp_commit();
    };

    load_tile(0);

    for (int chunk = 0; chunk < NC; chunk++) {
        if (chunk + 1 < NC) { load_tile(chunk + 1); cp_wait<1>(); }
        else                { cp_wait<0>(); }
        __syncthreads();

        const uint16_t* As = smh + (chunk & 1) * STAGE_H;
        const uint16_t* Bs = As + A_HALVES;
        uint32_t aBase = smem_u32(As) + (uint32_t)(((wm * 32 + lrow) * AS_ST + lcol) * 2);
        uint32_t bBase = smem_u32(Bs) + (uint32_t)((lrow * BS_ST + wn * 64 + lcol) * 2);

        #pragma unroll
        for (int ks = 0; ks < 4; ks++) {
            uint32_t a[2][4];
            #pragma unroll
            for (int mt = 0; mt < 2; mt++)
                ldsm_x4(a[mt], aBase + (uint32_t)((mt * 16 * AS_ST + ks * 16) * 2));

            uint32_t b[8][2];
            #pragma unroll
            for (int nb = 0; nb < 4; nb++) {
                uint32_t r[4];
                ldsm_x4_trans(r, bBase + (uint32_t)((ks * 16 * BS_ST + nb * 16) * 2));
                b[2 * nb][0]     = r[0];
                b[2 * nb][1]     = r[1];
                b[2 * nb + 1][0] = r[2];
                b[2 * nb + 1][1] = r[3];
            }
            #pragma unroll
            for (int nt = 0; nt < 8; nt++) {
                mma_f16_16n8k16(acc[0][nt], a[0], b[nt]);
                mma_f16_16n8k16(acc[1][nt], a[1], b[nt]);
            }
        }
        __syncthreads();
    }

    #pragma unroll
    for (int mt = 0; mt < 2; mt++) {
        #pragma unroll
        for (int nt = 0; nt < 8; nt++) {
            int col = n0 + wn * 64 + nt * 8 + 2 * tig;
            float b0 = bias[col], b1 = bias[col + 1];
            int r0 = m0 + wm * 32 + mt * 16 + gid;
            int r1 = r0 + 8;
            float v0 = acc[mt][nt][0] + b0;
            float v1 = acc[mt][nt][1] + b1;
            float v2 = acc[mt][nt][2] + b0;
            float v3 = acc[mt][nt][3] + b1;
            if (ACT == 1) {
                v0 = gelu_f(v0); v1 = gelu_f(v1);
                v2 = gelu_f(v2); v3 = gelu_f(v3);
            }
            if (r0 < M) {
                if (WF32) *(float2*)&Cf[(long)r0 * N + col] = make_float2(v0, v1);
                if (WF16) *(__half2*)&Ch[(long)r0 * N + col] = __floats2half2_rn(v0, v1);
            }
            if (r1 < M) {
                if (WF32) *(float2*)&Cf[(long)r1 * N + col] = make_float2(v2, v3);
                if (WF16) *(__half2*)&Ch[(long)r1 * N + col] = __floats2half2_rn(v2, v3);
            }
        }
    }
}

// ---------------------------------------------------------------------------
// Kernel: per-row LN of h2, sigmoid gate from h, residual update (+fp16 mirror)
// ---------------------------------------------------------------------------
__global__ __launch_bounds__(256)
void lngate_kernel(const float* __restrict__ ng, const float* __restrict__ nb,
                   const float* __restrict__ gwv) {
    __shared__ float red[256];
    int m = blockIdx.x, e = blockIdx.y;
    if (m >= d_counts[e]) return;
    int t = threadIdx.x;

    float* h = d_H + ((size_t)e * CAP + m) * D_FF;
    __half* h16 = d_H16 + ((size_t)e * CAP + m) * D_FF;
    const float* h2 = d_H2 + ((size_t)e * CAP + m) * D_FF;
    const float* ng_e = ng + (size_t)e * (N_LAYERS * D_FF);
    const float* nb_e = nb + (size_t)e * (N_LAYERS * D_FF);
    const float* gw_e = gwv + (size_t)e * (N_LAYERS * D_FF);

    float hv[4], h2v[4];
    float s = 0.f, sq = 0.f, dot = 0.f;
    #pragma unroll
    for (int c = 0; c < 4; c++) {
        int i = t + c * 256;
        hv[c] = h[i];
        h2v[c] = h2[i];
        s += h2v[c];
        dot = fmaf(hv[c], gw_e[i], dot);
    }
    float mean = reduce256(s, red) * (1.0f / D_FF);
    #pragma unroll
    for (int c = 0; c < 4; c++) { float d = h2v[c] - mean; sq += d * d; }
    float var = reduce256(sq, red) * (1.0f / D_FF);
    float dtot = reduce256(dot, red);
    float gate = 1.0f / (1.0f + expf(-dtot));
    float rstd = rsqrtf(var + 1e-5f);

    #pragma unroll
    for (int c = 0; c < 4; c++) {
        int i = t + c * 256;
        float hn = (h2v[c] - mean) * rstd * ng_e[i] + nb_e[i];
        float nv = hv[c] + gate * hn;
        h[i] = nv;
        h16[i] = __float2half(nv);
    }
}

// ---------------------------------------------------------------------------
// Kernel: final residual LN + scatter-add into output.
// ---------------------------------------------------------------------------
__global__ __launch_bounds__(256)
void final_kernel(const float* __restrict__ x,
                  const float* __restrict__ fng, const float* __restrict__ fnb,
                  float* __restrict__ out) {
    __shared__ float red[256];
    int m = blockIdx.x, e = blockIdx.y;
    if (m >= d_counts[e]) return;
    int t = threadIdx.x;
    int token = d_tlist[e * CAP + m];

    const float* orow = d_Ob + ((size_t)e * CAP + m) * D_MODEL;
    const float* xrow = x + (size_t)token * D_MODEL;
    const float* g = fng + (size_t)e * D_MODEL;
    const float* b = fnb + (size_t)e * D_MODEL;

    float v[2];
    float s = 0.f, sq = 0.f;
    #pragma unroll
    for (int c = 0; c < 2; c++) {
        int i = t + c * 256;
        v[c] = xrow[i] + orow[i];
        s += v[c];
    }
    float mean = reduce256(s, red) * (1.0f / D_MODEL);
    #pragma unroll
    for (int c = 0; c < 2; c++) { float d = v[c] - mean; sq += d * d; }
    float var = reduce256(sq, red) * (1.0f / D_MODEL);
    float rstd = rsqrtf(var + 1e-5f);

    #pragma unroll
    for (int c = 0; c < 2; c++) {
        int i = t + c * 256;
        float y = (v[c] - mean) * rstd * g[i] + b[i];
        atomicAdd(&out[(size_t)token * D_MODEL + i], y);
    }
}

// ---------------------------------------------------------------------------
// Launch — weight conversion forked onto a side stream so it overlaps
// routing/gather/early GEMMs. Event fork/join keeps the capture a DAG.
// Streams/events are created once on the (uncaptured) correctness call.
// ---------------------------------------------------------------------------
extern "C" void kernel_launch(void* const* d_in, const int* in_sizes, int n_in,
                              void* d_out, int out_size) {
    const float* x    = (const float*)d_in[0];
    const float* pw1  = (const float*)d_in[1];
    const float* pb1  = (const float*)d_in[2];
    const float* pg1  = (const float*)d_in[3];
    const float* pbb1 = (const float*)d_in[4];
    const float* pw2  = (const float*)d_in[5];
    const float* pb2  = (const float*)d_in[6];
    const float* Win  = (const float*)d_in[7];
    const float* b_in = (const float*)d_in[8];
    const float* W1   = (const float*)d_in[9];
    const float* b1   = (const float*)d_in[10];
    const float* W2   = (const float*)d_in[11];
    const float* b2   = (const float*)d_in[12];
    const float* ng   = (const float*)d_in[13];
    const float* nb   = (const float*)d_in[14];
    const float* gw   = (const float*)d_in[15];
    const float* Wout = (const float*)d_in[16];
    const float* bout = (const float*)d_in[17];
    const float* fng  = (const float*)d_in[18];
    const float* fnb  = (const float*)d_in[19];
    float* out = (float*)d_out;

    __half *Xg16, *H16, *A216, *Win16, *W116, *W216, *Wout16;
    float *H, *H2, *Ob;
    cudaGetSymbolAddress((void**)&Xg16, d_Xg16);
    cudaGetSymbolAddress((void**)&H,    d_H);
    cudaGetSymbolAddress((void**)&H16,  d_H16);
    cudaGetSymbolAddress((void**)&A216, d_A216);
    cudaGetSymbolAddress((void**)&H2,   d_H2);
    cudaGetSymbolAddress((void**)&Ob,   d_Ob);
    cudaGetSymbolAddress((void**)&Win16,  d_Win16);
    cudaGetSymbolAddress((void**)&W116,   d_W116);
    cudaGetSymbolAddress((void**)&W216,   d_W216);
    cudaGetSymbolAddress((void**)&Wout16, d_Wout16);

    cudaFuncSetAttribute(gemm_h<0,true,true>,  cudaFuncAttributeMaxDynamicSharedMemorySize, GEMM_SMEM);
    cudaFuncSetAttribute(gemm_h<1,false,true>, cudaFuncAttributeMaxDynamicSharedMemorySize, GEMM_SMEM);
    cudaFuncSetAttribute(gemm_h<0,true,false>, cudaFuncAttributeMaxDynamicSharedMemorySize, GEMM_SMEM);

    // one-time side-stream / event setup (correctness call runs uncaptured)
    static cudaStream_t s1 = nullptr;
    static cudaEvent_t evRoot = nullptr, evWin = nullptr, evW1 = nullptr,
                       evW2 = nullptr, evWout = nullptr;
    if (!s1) {
        cudaStreamCreateWithFlags(&s1, cudaStreamNonBlocking);
        cudaEventCreateWithFlags(&evRoot, cudaEventDisableTiming);
        cudaEventCreateWithFlags(&evWin,  cudaEventDisableTiming);
        cudaEventCreateWithFlags(&evW1,   cudaEventDisableTiming);
        cudaEventCreateWithFlags(&evW2,   cudaEventDisableTiming);
        cudaEventCreateWithFlags(&evWout, cudaEventDisableTiming);
    }

    // fork: weight conversion chain on s1
    cudaEventRecord(evRoot, 0);
    cudaStreamWaitEvent(s1, evRoot, 0);
    {
        long n;
        n = (long)N_EXPERTS * D_MODEL * D_FF / 4;
        conv_kernel<<<(unsigned)((n + 255) / 256), 256, 0, s1>>>((const float4*)Win, (h4*)Win16, n);
        cudaEventRecord(evWin, s1);
        n = (long)N_EXPERTS * N_LAYERS * D_FF * D_FF2 / 4;
        conv_kernel<<<(unsigned)((n + 255) / 256), 256, 0, s1>>>((const float4*)W1, (h4*)W116, n);
        cudaEventRecord(evW1, s1);
        n = (long)N_EXPERTS * N_LAYERS * D_FF2 * D_FF / 4;
        conv_kernel<<<(unsigned)((n + 255) / 256), 256, 0, s1>>>((const float4*)W2, (h4*)W216, n);
        cudaEventRecord(evW2, s1);
        n = (long)N_EXPERTS * D_FF * D_MODEL / 4;
        conv_kernel<<<(unsigned)((n + 255) / 256), 256, 0, s1>>>((const float4*)Wout, (h4*)Wout16, n);
        cudaEventRecord(evWout, s1);
    }

    // main chain on stream 0 (overlaps with conversions)
    cudaMemsetAsync(out, 0, (size_t)out_size * sizeof(float), 0);
    zero_counts_kernel<<<1, 32>>>();
    routing_kernel<<<N_TOKENS, 256>>>(x, pw1, pb1, pg1, pbb1, pw2, pb2);
    gather_kernel<<<dim3(CAP, N_EXPERTS), 128>>>(x);

    // H = Xg @ Win + b_in   (needs Win16)
    cudaStreamWaitEvent(0, evWin, 0);
    gemm_h<0,true,true><<<dim3(D_FF / 128, CAP / 128, N_EXPERTS), 256, GEMM_SMEM>>>(
        Xg16, (long)CAP * D_MODEL,
        Win16, (long)D_MODEL * D_FF,
        b_in, (long)D_FF,
        H, H16, (long)CAP * D_FF,
        D_FF, D_MODEL);

    cudaStreamWaitEvent(0, evW1, 0);   // W116 ready (both layers)
    for (int l = 0; l < N_LAYERS; l++) {
        // A2 = gelu(H @ W1[l] + b1[l])  -> fp16 only
        gemm_h<1,false,true><<<dim3(D_FF2 / 128, CAP / 128, N_EXPERTS), 256, GEMM_SMEM>>>(
            H16, (long)CAP * D_FF,
            W116 + (long)l * D_FF * D_FF2, (long)N_LAYERS * D_FF * D_FF2,
            b1 + (long)l * D_FF2, (long)N_LAYERS * D_FF2,
            nullptr, A216, (long)CAP * D_FF2,
            D_FF2, D_FF);
        // H2 = A2 @ W2[l] + b2[l]  -> fp32 only
        if (l == 0) cudaStreamWaitEvent(0, evW2, 0);   // W216 ready
        gemm_h<0,true,false><<<dim3(D_FF / 128, CAP / 128, N_EXPERTS), 256, GEMM_SMEM>>>(
            A216, (long)CAP * D_FF2,
            W216 + (long)l * D_FF2 * D_FF, (long)N_LAYERS * D_FF2 * D_FF,
            b2 + (long)l * D_FF, (long)N_LAYERS * D_FF,
            H2, nullptr, (long)CAP * D_FF,
            D_FF, D_FF2);
        // H += sigmoid(H.gw) * LN(H2); refresh H16
        lngate_kernel<<<dim3(CAP, N_EXPERTS), 256>>>(
            ng + (long)l * D_FF, nb + (long)l * D_FF, gw + (long)l * D_FF);
    }

    // Ob = H @ Wout + bout  (needs Wout16; joins s1 into stream 0)
    cudaStreamWaitEvent(0, evWout, 0);
    gemm_h<0,true,false><<<dim3(D_MODEL / 128, CAP / 128, N_EXPERTS), 256, GEMM_SMEM>>>(
        H16, (long)CAP * D_FF,
        Wout16, (long)D_FF * D_MODEL,
        bout, (long)D_MODEL,
        Ob, nullptr, (long)CAP * D_MODEL,
        D_MODEL, D_FF);

    final_kernel<<<dim3(CAP, N_EXPERTS), 256>>>(x, fng, fnb, out);
}

// round 17
// speedup vs baseline: 2.3008x; 1.1146x over previous
#include <cuda_runtime.h>
#include <cuda_fp16.h>
#include <cstdint>

// ---------------------------------------------------------------------------
// Problem constants
// ---------------------------------------------------------------------------
#define D_MODEL   512
#define D_HALF    256
#define D_FF      1024
#define D_FF2     2048
#define N_LAYERS  2
#define N_EXPERTS 8
#define N_TOKENS  2048
#define CAP       2048

// fp16 GEMM smem staging: tile 128(M) x 128(N) x 64(K)
#define AS_ST     72
#define BS_ST     136
#define A_HALVES  (128 * AS_ST)               // 9216
#define B_HALVES  (64 * BS_ST)                // 8704
#define STAGE_H   (A_HALVES + B_HALVES)       // 17920 halves
#define GEMM_SMEM (STAGE_H * 2 * 2)           // 71680 bytes -> 2 CTAs/SM

// routing tiling
#define TB        16
#define HB_ST     260
#define ROUT_SMEM ((TB * D_MODEL + TB * HB_ST) * 4)   // 49408 bytes

// ---------------------------------------------------------------------------
// Static scratch (no allocations allowed)
// ---------------------------------------------------------------------------
__device__ __half d_Xg16[(size_t)N_EXPERTS * CAP * D_MODEL];
__device__ float  d_H   [(size_t)N_EXPERTS * CAP * D_FF];
__device__ __half d_H16 [(size_t)N_EXPERTS * CAP * D_FF];
__device__ __half d_A216[(size_t)N_EXPERTS * CAP * D_FF2];
__device__ float  d_H2  [(size_t)N_EXPERTS * CAP * D_FF];
__device__ float  d_Ob  [(size_t)N_EXPERTS * CAP * D_MODEL];
__device__ int    d_counts[N_EXPERTS];
__device__ int    d_tlist[N_EXPERTS * CAP];
// fp16 weights, ORIGINAL layout [K][N] (no transpose)
__device__ __half d_Win16 [(size_t)N_EXPERTS * D_MODEL * D_FF];
__device__ __half d_W116  [(size_t)N_EXPERTS * N_LAYERS * D_FF * D_FF2];
__device__ __half d_W216  [(size_t)N_EXPERTS * N_LAYERS * D_FF2 * D_FF];
__device__ __half d_Wout16[(size_t)N_EXPERTS * D_FF * D_MODEL];

// ---------------------------------------------------------------------------
// Helpers
// ---------------------------------------------------------------------------
__device__ __forceinline__ float gelu_f(float v) {
    return 0.5f * v * (1.0f + erff(v * 0.70710678118654752440f));
}

__device__ __forceinline__ uint32_t smem_u32(const void* p) {
    uint32_t a;
    asm("{ .reg .u64 t; cvta.to.shared.u64 t, %1; cvt.u32.u64 %0, t; }" : "=r"(a) : "l"(p));
    return a;
}

__device__ __forceinline__ void cp16(uint32_t dst, const void* src, int szbytes) {
    asm volatile("cp.async.cg.shared.global [%0], [%1], 16, %2;"
                 :: "r"(dst), "l"(src), "r"(szbytes));
}
__device__ __forceinline__ void cp16f(uint32_t dst, const void* src) {
    asm volatile("cp.async.cg.shared.global [%0], [%1], 16;"
                 :: "r"(dst), "l"(src));
}
__device__ __forceinline__ void cp_commit() {
    asm volatile("cp.async.commit_group;" ::: "memory");
}
template<int N>
__device__ __forceinline__ void cp_wait() {
    asm volatile("cp.async.wait_group %0;" :: "n"(N) : "memory");
}

__device__ __forceinline__ void ldsm_x4(uint32_t* r, uint32_t addr) {
    asm volatile("ldmatrix.sync.aligned.m8n8.x4.shared.b16 {%0,%1,%2,%3}, [%4];"
                 : "=r"(r[0]), "=r"(r[1]), "=r"(r[2]), "=r"(r[3]) : "r"(addr));
}
__device__ __forceinline__ void ldsm_x4_trans(uint32_t* r, uint32_t addr) {
    asm volatile("ldmatrix.sync.aligned.m8n8.x4.trans.shared.b16 {%0,%1,%2,%3}, [%4];"
                 : "=r"(r[0]), "=r"(r[1]), "=r"(r[2]), "=r"(r[3]) : "r"(addr));
}

// m16n8k16 fp16 mma, fp32 accum
__device__ __forceinline__ void mma_f16_16n8k16(float* c, const uint32_t* a,
                                                const uint32_t* b) {
    asm volatile(
        "mma.sync.aligned.m16n8k16.row.col.f32.f16.f16.f32 "
        "{%0,%1,%2,%3}, {%4,%5,%6,%7}, {%8,%9}, {%0,%1,%2,%3};"
        : "+f"(c[0]), "+f"(c[1]), "+f"(c[2]), "+f"(c[3])
        : "r"(a[0]), "r"(a[1]), "r"(a[2]), "r"(a[3]), "r"(b[0]), "r"(b[1]));
}

__device__ __forceinline__ float reduce256(float v, float* red) {
    int t = threadIdx.x;
    red[t] = v;
    __syncthreads();
    #pragma unroll
    for (int s = 128; s > 0; s >>= 1) {
        if (t < s) red[t] += red[t + s];
        __syncthreads();
    }
    float r = red[0];
    __syncthreads();
    return r;
}

__device__ __forceinline__ void tf_round(uint32_t& a, uint32_t& b, int r) {
    a += b;
    b = (b << r) | (b >> (32 - r));
    b ^= a;
}

__device__ __forceinline__ uint2 threefry2x32(uint32_t k0, uint32_t k1,
                                              uint32_t x0, uint32_t x1) {
    uint32_t ks0 = k0, ks1 = k1, ks2 = k0 ^ k1 ^ 0x1BD11BDAu;
    x0 += ks0; x1 += ks1;
    tf_round(x0, x1, 13); tf_round(x0, x1, 15); tf_round(x0, x1, 26); tf_round(x0, x1, 6);
    x0 += ks1; x1 += ks2 + 1u;
    tf_round(x0, x1, 17); tf_round(x0, x1, 29); tf_round(x0, x1, 16); tf_round(x0, x1, 24);
    x0 += ks2; x1 += ks0 + 2u;
    tf_round(x0, x1, 13); tf_round(x0, x1, 15); tf_round(x0, x1, 26); tf_round(x0, x1, 6);
    x0 += ks0; x1 += ks1 + 3u;
    tf_round(x0, x1, 17); tf_round(x0, x1, 29); tf_round(x0, x1, 16); tf_round(x0, x1, 24);
    x0 += ks1; x1 += ks2 + 4u;
    tf_round(x0, x1, 13); tf_round(x0, x1, 15); tf_round(x0, x1, 26); tf_round(x0, x1, 6);
    x0 += ks2; x1 += ks0 + 5u;
    return make_uint2(x0, x1);
}

// ---------------------------------------------------------------------------
// Kernel: zero routing counters
// ---------------------------------------------------------------------------
__global__ void zero_counts_kernel() {
    if (threadIdx.x < N_EXPERTS) d_counts[threadIdx.x] = 0;
}

// ---------------------------------------------------------------------------
// Kernel: streaming fp32 -> fp16 convert (same layout, no transpose)
// ---------------------------------------------------------------------------
struct h4 { __half2 a, b; };
__global__ __launch_bounds__(256)
void conv_kernel(const float4* __restrict__ src, h4* __restrict__ dst, long n4) {
    long i = (long)blockIdx.x * 256 + threadIdx.x;
    if (i < n4) {
        float4 v = src[i];
        h4 o;
        o.a = __floats2half2_rn(v.x, v.y);
        o.b = __floats2half2_rn(v.z, v.w);
        dst[i] = o;
    }
}

// ---------------------------------------------------------------------------
// Kernel: tiled policy head + Gumbel top-2 routing.
// One block = TB(16) tokens, 256 threads (thread = output column).
// pw1 L2 traffic: 128 blocks x 512KB = 64MB (was 1GB with 1 block/token).
// ---------------------------------------------------------------------------
__global__ __launch_bounds__(256)
void routing_kernel(const float* __restrict__ x,
                    const float* __restrict__ pw1, const float* __restrict__ pb1,
                    const float* __restrict__ pg1, const float* __restrict__ pbb1,
                    const float* __restrict__ pw2, const float* __restrict__ pb2) {
    extern __shared__ float rs[];
    float* xs   = rs;                    // [TB][512]
    float* hbuf = rs + TB * D_MODEL;     // [TB][HB_ST]

    int tid = threadIdx.x;
    int tok0 = blockIdx.x * TB;

    // load TB rows of x (rows are contiguous)
    const float4* xsrc = (const float4*)(x + (size_t)tok0 * D_MODEL);
    float4* xdst = (float4*)xs;
    #pragma unroll
    for (int i = 0; i < (TB * D_MODEL / 4) / 256; i++)
        xdst[i * 256 + tid] = xsrc[i * 256 + tid];
    __syncthreads();

    // h1[tok][t] = x[tok] . pw1[:,t] + pb1[t], fp32, same per-k order as before
    int t = tid;
    float acc[TB];
    float b0 = pb1[t];
    #pragma unroll
    for (int tok = 0; tok < TB; tok++) acc[tok] = b0;
    for (int k4 = 0; k4 < D_MODEL / 4; k4++) {
        float w0 = pw1[(4 * k4 + 0) * D_HALF + t];
        float w1 = pw1[(4 * k4 + 1) * D_HALF + t];
        float w2 = pw1[(4 * k4 + 2) * D_HALF + t];
        float w3 = pw1[(4 * k4 + 3) * D_HALF + t];
        #pragma unroll
        for (int tok = 0; tok < TB; tok++) {
            float4 xv = *(const float4*)&xs[tok * D_MODEL + 4 * k4];
            acc[tok] = fmaf(xv.w, w3, fmaf(xv.z, w2,
                       fmaf(xv.y, w1, fmaf(xv.x, w0, acc[tok]))));
        }
    }
    #pragma unroll
    for (int tok = 0; tok < TB; tok++) hbuf[tok * HB_ST + t] = acc[tok];
    __syncthreads();

    // warp per token (8 warps x 2 tokens): LN -> GELU -> logits -> Gumbel top-2
    int wrp = tid >> 5, lane = tid & 31;
    float g1v[8], bbv[8];
    #pragma unroll
    for (int c = 0; c < 8; c++) {
        g1v[c] = pg1[lane + 32 * c];
        bbv[c] = pbb1[lane + 32 * c];
    }
    #pragma unroll
    for (int s = 0; s < TB / 8; s++) {
        int tok = wrp * (TB / 8) + s;
        float h[8], sum = 0.f;
        #pragma unroll
        for (int c = 0; c < 8; c++) {
            h[c] = hbuf[tok * HB_ST + lane + 32 * c];
            sum += h[c];
        }
        #pragma unroll
        for (int o = 16; o; o >>= 1) sum += __shfl_xor_sync(0xffffffffu, sum, o);
        float mean = sum * (1.0f / D_HALF);
        float sq = 0.f;
        #pragma unroll
        for (int c = 0; c < 8; c++) { float d = h[c] - mean; sq += d * d; }
        #pragma unroll
        for (int o = 16; o; o >>= 1) sq += __shfl_xor_sync(0xffffffffu, sq, o);
        float rstd = rsqrtf(sq * (1.0f / D_HALF) + 1e-5f);
        float g[8];
        #pragma unroll
        for (int c = 0; c < 8; c++)
            g[c] = gelu_f((h[c] - mean) * rstd * g1v[c] + bbv[c]);

        float lg[8];
        #pragma unroll
        for (int e = 0; e < 8; e++) {
            float p = 0.f;
            #pragma unroll
            for (int c = 0; c < 8; c++)
                p = fmaf(g[c], pw2[(lane + 32 * c) * N_EXPERTS + e], p);
            #pragma unroll
            for (int o = 16; o; o >>= 1) p += __shfl_xor_sync(0xffffffffu, p, o);
            lg[e] = p;
        }

        if (lane == 0) {
            int token = tok0 + tok;
            float sc[8];
            #pragma unroll
            for (int e = 0; e < 8; e++) {
                float l = lg[e] + pb2[e];
                // partitionable threefry: counter (0, i), bits = out0 ^ out1
                uint32_t idx = (uint32_t)(token * N_EXPERTS + e);
                uint2 r = threefry2x32(0u, 42u, 0u, idx);
                uint32_t bits = r.x ^ r.y;
                float u = __uint_as_float((bits >> 9) | 0x3f800000u) - 1.0f;
                float gn = -logf(-logf(u + 1e-10f) + 1e-10f);
                sc[e] = l + gn;
            }
            int e1 = 0; float v1 = sc[0];
            #pragma unroll
            for (int e = 1; e < N_EXPERTS; e++)
                if (sc[e] > v1) { v1 = sc[e]; e1 = e; }
            int e2 = -1; float v2 = -1e30f;
            #pragma unroll
            for (int e = 0; e < N_EXPERTS; e++) {
                if (e == e1) continue;
                if (sc[e] > v2) { v2 = sc[e]; e2 = e; }
            }
            int p = atomicAdd(&d_counts[e1], 1);
            d_tlist[e1 * CAP + p] = token;
            p = atomicAdd(&d_counts[e2], 1);
            d_tlist[e2 * CAP + p] = token;
        }
    }
}

// ---------------------------------------------------------------------------
// Kernel: gather selected token rows, converting to fp16
// ---------------------------------------------------------------------------
__global__ void gather_kernel(const float* __restrict__ x) {
    int m = blockIdx.x, e = blockIdx.y;
    if (m >= d_counts[e]) return;
    int token = d_tlist[e * CAP + m];
    const float4* src = (const float4*)(x + (size_t)token * D_MODEL);
    __half2* dst = (__half2*)(d_Xg16 + ((size_t)e * CAP + m) * D_MODEL);
    float4 v = src[threadIdx.x];
    dst[2 * threadIdx.x]     = __floats2half2_rn(v.x, v.y);
    dst[2 * threadIdx.x + 1] = __floats2half2_rn(v.z, v.w);
}

// ---------------------------------------------------------------------------
// fp16 tensor-core GEMM, cp.async 2-stage ping-pong, ldmatrix fragments.
// (unchanged — proven best)
// ---------------------------------------------------------------------------
template<int ACT, bool WF32, bool WF16>
__global__ __launch_bounds__(256, 2)
void gemm_h(const __half* __restrict__ Aall, long strideA,
            const __half* __restrict__ Ball, long strideB,
            const float* __restrict__ biasAll, long strideBias,
            float* __restrict__ Cfall, __half* __restrict__ Chall, long strideC,
            int N, int K) {
    extern __shared__ __align__(16) uint16_t smh[];

    int e = blockIdx.z;
    int M = d_counts[e];
    int m0 = blockIdx.y * 128;
    if (m0 >= M) return;
    int n0 = blockIdx.x * 128;

    const __half* A = Aall + (long)e * strideA;
    const __half* B = Ball + (long)e * strideB;
    const float* bias = biasAll + (long)e * strideBias;
    float*  Cf = WF32 ? Cfall + (long)e * strideC : nullptr;
    __half* Ch = WF16 ? Chall + (long)e * strideC : nullptr;

    int tid  = threadIdx.x;
    int wid  = tid >> 5;
    int lane = tid & 31;
    int wm = wid >> 1;
    int wn = wid & 1;
    int gid = lane >> 2;
    int tig = lane & 3;

    int lrow = (lane & 7) + 8 * ((lane >> 3) & 1);
    int lcol = 8 * (lane >> 4);

    float acc[2][8][4];
    #pragma unroll
    for (int i = 0; i < 2; i++)
        #pragma unroll
        for (int j = 0; j < 8; j++)
            #pragma unroll
            for (int c = 0; c < 4; c++) acc[i][j][c] = 0.0f;

    const int NC = K >> 6;

    auto load_tile = [&](int chunk) {
        uint16_t* As = smh + (chunk & 1) * STAGE_H;
        uint16_t* Bs = As + A_HALVES;
        int k0 = chunk << 6;
        #pragma unroll
        for (int i = 0; i < 4; i++) {
            int idx = i * 256 + tid;
            int r = idx >> 3, seg = idx & 7;
            int rr = m0 + r;
            int sz = (rr < M) ? 16 : 0;
            int rc = (rr < M) ? rr : 0;
            cp16(smem_u32(&As[r * AS_ST + seg * 8]),
                 &A[(long)rc * K + k0 + seg * 8], sz);
        }
        #pragma unroll
        for (int i = 0; i < 4; i++) {
            int idx = i * 256 + tid;
            int r = idx >> 4, seg = idx & 15;
            cp16f(smem_u32(&Bs[r * BS_ST + seg * 8]),
                  &B[(long)(k0 + r) * N + n0 + seg * 8]);
        }
        cp_commit();
    };

    load_tile(0);

    for (int chunk = 0; chunk < NC; chunk++) {
        if (chunk + 1 < NC) { load_tile(chunk + 1); cp_wait<1>(); }
        else                { cp_wait<0>(); }
        __syncthreads();

        const uint16_t* As = smh + (chunk & 1) * STAGE_H;
        const uint16_t* Bs = As + A_HALVES;
        uint32_t aBase = smem_u32(As) + (uint32_t)(((wm * 32 + lrow) * AS_ST + lcol) * 2);
        uint32_t bBase = smem_u32(Bs) + (uint32_t)((lrow * BS_ST + wn * 64 + lcol) * 2);

        #pragma unroll
        for (int ks = 0; ks < 4; ks++) {
            uint32_t a[2][4];
            #pragma unroll
            for (int mt = 0; mt < 2; mt++)
                ldsm_x4(a[mt], aBase + (uint32_t)((mt * 16 * AS_ST + ks * 16) * 2));

            uint32_t b[8][2];
            #pragma unroll
            for (int nb = 0; nb < 4; nb++) {
                uint32_t r[4];
                ldsm_x4_trans(r, bBase + (uint32_t)((ks * 16 * BS_ST + nb * 16) * 2));
                b[2 * nb][0]     = r[0];
                b[2 * nb][1]     = r[1];
                b[2 * nb + 1][0] = r[2];
                b[2 * nb + 1][1] = r[3];
            }
            #pragma unroll
            for (int nt = 0; nt < 8; nt++) {
                mma_f16_16n8k16(acc[0][nt], a[0], b[nt]);
                mma_f16_16n8k16(acc[1][nt], a[1], b[nt]);
            }
        }
        __syncthreads();
    }

    #pragma unroll
    for (int mt = 0; mt < 2; mt++) {
        #pragma unroll
        for (int nt = 0; nt < 8; nt++) {
            int col = n0 + wn * 64 + nt * 8 + 2 * tig;
            float b0 = bias[col], b1 = bias[col + 1];
            int r0 = m0 + wm * 32 + mt * 16 + gid;
            int r1 = r0 + 8;
            float v0 = acc[mt][nt][0] + b0;
            float v1 = acc[mt][nt][1] + b1;
            float v2 = acc[mt][nt][2] + b0;
            float v3 = acc[mt][nt][3] + b1;
            if (ACT == 1) {
                v0 = gelu_f(v0); v1 = gelu_f(v1);
                v2 = gelu_f(v2); v3 = gelu_f(v3);
            }
            if (r0 < M) {
                if (WF32) *(float2*)&Cf[(long)r0 * N + col] = make_float2(v0, v1);
                if (WF16) *(__half2*)&Ch[(long)r0 * N + col] = __floats2half2_rn(v0, v1);
            }
            if (r1 < M) {
                if (WF32) *(float2*)&Cf[(long)r1 * N + col] = make_float2(v2, v3);
                if (WF16) *(__half2*)&Ch[(long)r1 * N + col] = __floats2half2_rn(v2, v3);
            }
        }
    }
}

// ---------------------------------------------------------------------------
// Kernel: per-row LN of h2, sigmoid gate from h, residual update (+fp16 mirror)
// ---------------------------------------------------------------------------
__global__ __launch_bounds__(256)
void lngate_kernel(const float* __restrict__ ng, const float* __restrict__ nb,
                   const float* __restrict__ gwv) {
    __shared__ float red[256];
    int m = blockIdx.x, e = blockIdx.y;
    if (m >= d_counts[e]) return;
    int t = threadIdx.x;

    float* h = d_H + ((size_t)e * CAP + m) * D_FF;
    __half* h16 = d_H16 + ((size_t)e * CAP + m) * D_FF;
    const float* h2 = d_H2 + ((size_t)e * CAP + m) * D_FF;
    const float* ng_e = ng + (size_t)e * (N_LAYERS * D_FF);
    const float* nb_e = nb + (size_t)e * (N_LAYERS * D_FF);
    const float* gw_e = gwv + (size_t)e * (N_LAYERS * D_FF);

    float hv[4], h2v[4];
    float s = 0.f, sq = 0.f, dot = 0.f;
    #pragma unroll
    for (int c = 0; c < 4; c++) {
        int i = t + c * 256;
        hv[c] = h[i];
        h2v[c] = h2[i];
        s += h2v[c];
        dot = fmaf(hv[c], gw_e[i], dot);
    }
    float mean = reduce256(s, red) * (1.0f / D_FF);
    #pragma unroll
    for (int c = 0; c < 4; c++) { float d = h2v[c] - mean; sq += d * d; }
    float var = reduce256(sq, red) * (1.0f / D_FF);
    float dtot = reduce256(dot, red);
    float gate = 1.0f / (1.0f + expf(-dtot));
    float rstd = rsqrtf(var + 1e-5f);

    #pragma unroll
    for (int c = 0; c < 4; c++) {
        int i = t + c * 256;
        float hn = (h2v[c] - mean) * rstd * ng_e[i] + nb_e[i];
        float nv = hv[c] + gate * hn;
        h[i] = nv;
        h16[i] = __float2half(nv);
    }
}

// ---------------------------------------------------------------------------
// Kernel: final residual LN + scatter-add into output.
// ---------------------------------------------------------------------------
__global__ __launch_bounds__(256)
void final_kernel(const float* __restrict__ x,
                  const float* __restrict__ fng, const float* __restrict__ fnb,
                  float* __restrict__ out) {
    __shared__ float red[256];
    int m = blockIdx.x, e = blockIdx.y;
    if (m >= d_counts[e]) return;
    int t = threadIdx.x;
    int token = d_tlist[e * CAP + m];

    const float* orow = d_Ob + ((size_t)e * CAP + m) * D_MODEL;
    const float* xrow = x + (size_t)token * D_MODEL;
    const float* g = fng + (size_t)e * D_MODEL;
    const float* b = fnb + (size_t)e * D_MODEL;

    float v[2];
    float s = 0.f, sq = 0.f;
    #pragma unroll
    for (int c = 0; c < 2; c++) {
        int i = t + c * 256;
        v[c] = xrow[i] + orow[i];
        s += v[c];
    }
    float mean = reduce256(s, red) * (1.0f / D_MODEL);
    #pragma unroll
    for (int c = 0; c < 2; c++) { float d = v[c] - mean; sq += d * d; }
    float var = reduce256(sq, red) * (1.0f / D_MODEL);
    float rstd = rsqrtf(var + 1e-5f);

    #pragma unroll
    for (int c = 0; c < 2; c++) {
        int i = t + c * 256;
        float y = (v[c] - mean) * rstd * g[i] + b[i];
        atomicAdd(&out[(size_t)token * D_MODEL + i], y);
    }
}

// ---------------------------------------------------------------------------
// Launch — conv fork kept (harmless); routing now tiled.
// ---------------------------------------------------------------------------
extern "C" void kernel_launch(void* const* d_in, const int* in_sizes, int n_in,
                              void* d_out, int out_size) {
    const float* x    = (const float*)d_in[0];
    const float* pw1  = (const float*)d_in[1];
    const float* pb1  = (const float*)d_in[2];
    const float* pg1  = (const float*)d_in[3];
    const float* pbb1 = (const float*)d_in[4];
    const float* pw2  = (const float*)d_in[5];
    const float* pb2  = (const float*)d_in[6];
    const float* Win  = (const float*)d_in[7];
    const float* b_in = (const float*)d_in[8];
    const float* W1   = (const float*)d_in[9];
    const float* b1   = (const float*)d_in[10];
    const float* W2   = (const float*)d_in[11];
    const float* b2   = (const float*)d_in[12];
    const float* ng   = (const float*)d_in[13];
    const float* nb   = (const float*)d_in[14];
    const float* gw   = (const float*)d_in[15];
    const float* Wout = (const float*)d_in[16];
    const float* bout = (const float*)d_in[17];
    const float* fng  = (const float*)d_in[18];
    const float* fnb  = (const float*)d_in[19];
    float* out = (float*)d_out;

    __half *Xg16, *H16, *A216, *Win16, *W116, *W216, *Wout16;
    float *H, *H2, *Ob;
    cudaGetSymbolAddress((void**)&Xg16, d_Xg16);
    cudaGetSymbolAddress((void**)&H,    d_H);
    cudaGetSymbolAddress((void**)&H16,  d_H16);
    cudaGetSymbolAddress((void**)&A216, d_A216);
    cudaGetSymbolAddress((void**)&H2,   d_H2);
    cudaGetSymbolAddress((void**)&Ob,   d_Ob);
    cudaGetSymbolAddress((void**)&Win16,  d_Win16);
    cudaGetSymbolAddress((void**)&W116,   d_W116);
    cudaGetSymbolAddress((void**)&W216,   d_W216);
    cudaGetSymbolAddress((void**)&Wout16, d_Wout16);

    cudaFuncSetAttribute(gemm_h<0,true,true>,  cudaFuncAttributeMaxDynamicSharedMemorySize, GEMM_SMEM);
    cudaFuncSetAttribute(gemm_h<1,false,true>, cudaFuncAttributeMaxDynamicSharedMemorySize, GEMM_SMEM);
    cudaFuncSetAttribute(gemm_h<0,true,false>, cudaFuncAttributeMaxDynamicSharedMemorySize, GEMM_SMEM);
    cudaFuncSetAttribute(routing_kernel, cudaFuncAttributeMaxDynamicSharedMemorySize, ROUT_SMEM);

    // one-time side-stream / event setup (correctness call runs uncaptured)
    static cudaStream_t s1 = nullptr;
    static cudaEvent_t evRoot = nullptr, evWin = nullptr, evW1 = nullptr,
                       evW2 = nullptr, evWout = nullptr;
    if (!s1) {
        cudaStreamCreateWithFlags(&s1, cudaStreamNonBlocking);
        cudaEventCreateWithFlags(&evRoot, cudaEventDisableTiming);
        cudaEventCreateWithFlags(&evWin,  cudaEventDisableTiming);
        cudaEventCreateWithFlags(&evW1,   cudaEventDisableTiming);
        cudaEventCreateWithFlags(&evW2,   cudaEventDisableTiming);
        cudaEventCreateWithFlags(&evWout, cudaEventDisableTiming);
    }

    // fork: weight conversion chain on s1
    cudaEventRecord(evRoot, 0);
    cudaStreamWaitEvent(s1, evRoot, 0);
    {
        long n;
        n = (long)N_EXPERTS * D_MODEL * D_FF / 4;
        conv_kernel<<<(unsigned)((n + 255) / 256), 256, 0, s1>>>((const float4*)Win, (h4*)Win16, n);
        cudaEventRecord(evWin, s1);
        n = (long)N_EXPERTS * N_LAYERS * D_FF * D_FF2 / 4;
        conv_kernel<<<(unsigned)((n + 255) / 256), 256, 0, s1>>>((const float4*)W1, (h4*)W116, n);
        cudaEventRecord(evW1, s1);
        n = (long)N_EXPERTS * N_LAYERS * D_FF2 * D_FF / 4;
        conv_kernel<<<(unsigned)((n + 255) / 256), 256, 0, s1>>>((const float4*)W2, (h4*)W216, n);
        cudaEventRecord(evW2, s1);
        n = (long)N_EXPERTS * D_FF * D_MODEL / 4;
        conv_kernel<<<(unsigned)((n + 255) / 256), 256, 0, s1>>>((const float4*)Wout, (h4*)Wout16, n);
        cudaEventRecord(evWout, s1);
    }

    // main chain on stream 0
    cudaMemsetAsync(out, 0, (size_t)out_size * sizeof(float), 0);
    zero_counts_kernel<<<1, 32>>>();
    routing_kernel<<<N_TOKENS / TB, 256, ROUT_SMEM>>>(x, pw1, pb1, pg1, pbb1, pw2, pb2);
    gather_kernel<<<dim3(CAP, N_EXPERTS), 128>>>(x);

    // H = Xg @ Win + b_in   (needs Win16)
    cudaStreamWaitEvent(0, evWin, 0);
    gemm_h<0,true,true><<<dim3(D_FF / 128, CAP / 128, N_EXPERTS), 256, GEMM_SMEM>>>(
        Xg16, (long)CAP * D_MODEL,
        Win16, (long)D_MODEL * D_FF,
        b_in, (long)D_FF,
        H, H16, (long)CAP * D_FF,
        D_FF, D_MODEL);

    cudaStreamWaitEvent(0, evW1, 0);
    for (int l = 0; l < N_LAYERS; l++) {
        gemm_h<1,false,true><<<dim3(D_FF2 / 128, CAP / 128, N_EXPERTS), 256, GEMM_SMEM>>>(
            H16, (long)CAP * D_FF,
            W116 + (long)l * D_FF * D_FF2, (long)N_LAYERS * D_FF * D_FF2,
            b1 + (long)l * D_FF2, (long)N_LAYERS * D_FF2,
            nullptr, A216, (long)CAP * D_FF2,
            D_FF2, D_FF);
        if (l == 0) cudaStreamWaitEvent(0, evW2, 0);
        gemm_h<0,true,false><<<dim3(D_FF / 128, CAP / 128, N_EXPERTS), 256, GEMM_SMEM>>>(
            A216, (long)CAP * D_FF2,
            W216 + (long)l * D_FF2 * D_FF, (long)N_LAYERS * D_FF2 * D_FF,
            b2 + (long)l * D_FF, (long)N_LAYERS * D_FF,
            H2, nullptr, (long)CAP * D_FF,
            D_FF, D_FF2);
        lngate_kernel<<<dim3(CAP, N_EXPERTS), 256>>>(
            ng + (long)l * D_FF, nb + (long)l * D_FF, gw + (long)l * D_FF);
    }

    cudaStreamWaitEvent(0, evWout, 0);
    gemm_h<0,true,false><<<dim3(D_MODEL / 128, CAP / 128, N_EXPERTS), 256, GEMM_SMEM>>>(
        H16, (long)CAP * D_FF,
        Wout16, (long)D_FF * D_MODEL,
        bout, (long)D_MODEL,
        Ob, nullptr, (long)CAP * D_MODEL,
        D_MODEL, D_FF);

    final_kernel<<<dim3(CAP, N_EXPERTS), 256>>>(x, fng, fnb, out);
}